// round 14
// baseline (speedup 1.0000x reference)
#include <cuda_runtime.h>
#include <cuda_bf16.h>
#include <math.h>
#include <stdint.h>

// Problem constants (fixed shapes from setup_inputs)
#define BB  8
#define CC  192
#define HH  56
#define WW  56
#define NN  3136            // H*W
#define CC2 384             // 2*C
#define CG  96              // C2/4
#define KNB 9               // K_NEIGHBORS
#define BNEPS 1e-5f
#define KTOT 576            // 3*CC  (hi|hi|lo concat)
#define KSLAB 32
#define NSLABS 18           // KTOT/KSLAB

// ---------------- scratch (static device globals; no runtime alloc) --------
__device__ float d_R   [56 * 56];                          // rel position table
__device__ float d_h   [(size_t)BB * NN * CC];             // 19.3 MB
__device__ __nv_bfloat16 d_xa[(size_t)BB * NN * KTOT];     // 28.9 MB  [hi|hi|lo]
__device__ __nv_bfloat16 d_xb[(size_t)BB * NN * KTOT];     // 28.9 MB  [hi|lo|hi]
__device__ float d_sq  [BB * NN];
__device__ float d_dist[(size_t)BB * NN * NN];             // 314.7 MB
__device__ float d_gbuf[(size_t)BB * NN * CC2];            // 38.6 MB
__device__ float d_ybuf[(size_t)BB * NN * CC2];            // 38.6 MB
__device__ float d_obuf[(size_t)BB * NN * CC];             // 19.3 MB

__device__ __forceinline__ uint32_t smem_u32(const void* p) {
    uint32_t a;
    asm("{ .reg .u64 t; cvta.to.shared.u64 t, %1; cvt.u32.u64 %0, t; }"
        : "=r"(a) : "l"(p));
    return a;
}

// ---------------- rel position table: R[a][b] = -2/C * emb(a).emb(b) --------
__global__ void rel_table_kernel() {
    int p = blockIdx.x * 128 + threadIdx.x;
    if (p >= 56 * 56) return;
    int a = p / 56, b = p - (p / 56) * 56;
    float s = 0.0f;
#pragma unroll 1
    for (int i = 0; i < 48; i++) {
        float wv = expf(-logf(10000.0f) * (float)i / 48.0f);
        float sa, ca, sb, cb;
        sincosf((float)a * wv, &sa, &ca);
        sincosf((float)b * wv, &sb, &cb);
        s += sa * sb + ca * cb;
    }
    d_R[p] = (-2.0f / (float)CC) * s;
}

// ---------------- 128x128x16 double-buffered SGEMM (modes 0,3,4) -----------
template <int MODE>
__global__ void __launch_bounds__(256, 2)
gemm_kernel(const float* __restrict__ Ain, const float* __restrict__ Bin,
            const float* __restrict__ q0, const float* __restrict__ q1,
            const float* __restrict__ q2, const float* __restrict__ q3,
            const float* __restrict__ q4)
{
    constexpr bool AKM = (MODE == 0);     // A stored K-major

    int M, Nc, K, lda, ldb;
    const float* A;
    const float* B;
    const int bz = blockIdx.z;

    if (MODE == 0) {
        A = Ain + (size_t)bz * CC * NN;  B = Bin;
        M = NN; Nc = CC; K = CC; lda = NN; ldb = CC;
    } else if (MODE == 3) {
        int b = bz >> 2, g = bz & 3;
        A = d_gbuf + (size_t)b * NN * CC2 + g * CG;
        B = Bin + (size_t)g * CG * CG;
        M = NN; Nc = CG; K = CG; lda = CC2; ldb = CG;
    } else {
        A = d_ybuf; B = Bin;
        M = BB * NN; Nc = CC; K = CC2; lda = CC2; ldb = CC2;
    }

    __shared__ float As[2][16][128];
    __shared__ float Bs[2][16][128];

    const int tid = threadIdx.x;
    const int tx = tid & 15;
    const int ty = tid >> 4;
    const int m0 = blockIdx.y * 128;
    const int n0 = blockIdx.x * 128;

    const float* aptr0;
    const float* aptr1;
    int a_km_k = 0, a_km_m = 0;
    int a_rm_r = 0, a_rm_kq = 0;
    if (AKM) {
        a_km_k = tid >> 5;
        a_km_m = (tid & 31) * 4;
        int mc = min(m0 + a_km_m, M - 4);
        aptr0 = A + (size_t)a_km_k * lda + mc;
        aptr1 = A + (size_t)(a_km_k + 8) * lda + mc;
    } else {
        a_rm_r  = tid >> 1;
        a_rm_kq = (tid & 1) * 8;
        int rc = min(m0 + a_rm_r, M - 1);
        aptr0 = A + (size_t)rc * lda + a_rm_kq;
        aptr1 = aptr0 + 4;
    }
    const int b_rm_r  = tid >> 1;
    const int b_rm_kq = (tid & 1) * 8;
    const float* bptr0 = B + (size_t)min(n0 + b_rm_r, Nc - 1) * ldb + b_rm_kq;
    const float* bptr1 = bptr0 + 4;

    float4 ra0, ra1, rb0, rb1;
    ra0 = *reinterpret_cast<const float4*>(aptr0);
    ra1 = *reinterpret_cast<const float4*>(aptr1);
    rb0 = *reinterpret_cast<const float4*>(bptr0);
    rb1 = *reinterpret_cast<const float4*>(bptr1);
    if (AKM) {
        *reinterpret_cast<float4*>(&As[0][a_km_k][a_km_m])     = ra0;
        *reinterpret_cast<float4*>(&As[0][a_km_k + 8][a_km_m]) = ra1;
    } else {
        As[0][a_rm_kq + 0][a_rm_r] = ra0.x; As[0][a_rm_kq + 1][a_rm_r] = ra0.y;
        As[0][a_rm_kq + 2][a_rm_r] = ra0.z; As[0][a_rm_kq + 3][a_rm_r] = ra0.w;
        As[0][a_rm_kq + 4][a_rm_r] = ra1.x; As[0][a_rm_kq + 5][a_rm_r] = ra1.y;
        As[0][a_rm_kq + 6][a_rm_r] = ra1.z; As[0][a_rm_kq + 7][a_rm_r] = ra1.w;
    }
    Bs[0][b_rm_kq + 0][b_rm_r] = rb0.x; Bs[0][b_rm_kq + 1][b_rm_r] = rb0.y;
    Bs[0][b_rm_kq + 2][b_rm_r] = rb0.z; Bs[0][b_rm_kq + 3][b_rm_r] = rb0.w;
    Bs[0][b_rm_kq + 4][b_rm_r] = rb1.x; Bs[0][b_rm_kq + 5][b_rm_r] = rb1.y;
    Bs[0][b_rm_kq + 6][b_rm_r] = rb1.z; Bs[0][b_rm_kq + 7][b_rm_r] = rb1.w;
    __syncthreads();

    float acc[8][8];
#pragma unroll
    for (int i = 0; i < 8; i++)
#pragma unroll
        for (int j = 0; j < 8; j++) acc[i][j] = 0.0f;

    const int T = K >> 4;
    for (int t = 0; t < T; t++) {
        const int cur = t & 1;
        if (t + 1 < T) {
            if (AKM) { aptr0 += (size_t)16 * lda; aptr1 += (size_t)16 * lda; }
            else     { aptr0 += 16;               aptr1 += 16; }
            bptr0 += 16; bptr1 += 16;
            ra0 = *reinterpret_cast<const float4*>(aptr0);
            ra1 = *reinterpret_cast<const float4*>(aptr1);
            rb0 = *reinterpret_cast<const float4*>(bptr0);
            rb1 = *reinterpret_cast<const float4*>(bptr1);
        }
#pragma unroll
        for (int kk = 0; kk < 16; kk++) {
            float af[8], bf[8];
            *reinterpret_cast<float4*>(&af[0]) = *reinterpret_cast<const float4*>(&As[cur][kk][ty * 4]);
            *reinterpret_cast<float4*>(&af[4]) = *reinterpret_cast<const float4*>(&As[cur][kk][64 + ty * 4]);
            *reinterpret_cast<float4*>(&bf[0]) = *reinterpret_cast<const float4*>(&Bs[cur][kk][tx * 4]);
            *reinterpret_cast<float4*>(&bf[4]) = *reinterpret_cast<const float4*>(&Bs[cur][kk][64 + tx * 4]);
#pragma unroll
            for (int i = 0; i < 8; i++)
#pragma unroll
                for (int j = 0; j < 8; j++) acc[i][j] += af[i] * bf[j];
        }
        if (t + 1 < T) {
            const int nxt = cur ^ 1;
            if (AKM) {
                *reinterpret_cast<float4*>(&As[nxt][a_km_k][a_km_m])     = ra0;
                *reinterpret_cast<float4*>(&As[nxt][a_km_k + 8][a_km_m]) = ra1;
            } else {
                As[nxt][a_rm_kq + 0][a_rm_r] = ra0.x; As[nxt][a_rm_kq + 1][a_rm_r] = ra0.y;
                As[nxt][a_rm_kq + 2][a_rm_r] = ra0.z; As[nxt][a_rm_kq + 3][a_rm_r] = ra0.w;
                As[nxt][a_rm_kq + 4][a_rm_r] = ra1.x; As[nxt][a_rm_kq + 5][a_rm_r] = ra1.y;
                As[nxt][a_rm_kq + 6][a_rm_r] = ra1.z; As[nxt][a_rm_kq + 7][a_rm_r] = ra1.w;
            }
            Bs[nxt][b_rm_kq + 0][b_rm_r] = rb0.x; Bs[nxt][b_rm_kq + 1][b_rm_r] = rb0.y;
            Bs[nxt][b_rm_kq + 2][b_rm_r] = rb0.z; Bs[nxt][b_rm_kq + 3][b_rm_r] = rb0.w;
            Bs[nxt][b_rm_kq + 4][b_rm_r] = rb1.x; Bs[nxt][b_rm_kq + 5][b_rm_r] = rb1.y;
            Bs[nxt][b_rm_kq + 6][b_rm_r] = rb1.z; Bs[nxt][b_rm_kq + 7][b_rm_r] = rb1.w;
        }
        __syncthreads();
    }

    int rows[8], cols[8];
#pragma unroll
    for (int i = 0; i < 4; i++) {
        rows[i]     = m0 + ty * 4 + i;
        rows[i + 4] = m0 + 64 + ty * 4 + i;
        cols[i]     = n0 + tx * 4 + i;
        cols[i + 4] = n0 + 64 + tx * 4 + i;
    }

    if (MODE == 0) {
        float sc[8], bi[8];
#pragma unroll
        for (int j = 0; j < 8; j++) {
            if (cols[j] < Nc) {
                float s = q1[cols[j]] * rsqrtf(q4[cols[j]] + BNEPS);
                sc[j] = s;
                bi[j] = (q0[cols[j]] - q3[cols[j]]) * s + q2[cols[j]];
            } else { sc[j] = 0.f; bi[j] = 0.f; }
        }
        float* hb = d_h + (size_t)bz * NN * CC;
#pragma unroll
        for (int i = 0; i < 8; i++) {
            if (rows[i] >= M) continue;
#pragma unroll
            for (int j = 0; j < 8; j++)
                if (cols[j] < Nc)
                    hb[(size_t)rows[i] * CC + cols[j]] = acc[i][j] * sc[j] + bi[j];
        }
    } else if (MODE == 3) {
        int b = bz >> 2, g = bz & 3;
        float sc[8], bi[8];
        int ch[8];
#pragma unroll
        for (int j = 0; j < 8; j++) {
            ch[j] = g * CG + cols[j];
            if (cols[j] < Nc) {
                float s = q1[ch[j]] * rsqrtf(q4[ch[j]] + BNEPS);
                sc[j] = s;
                bi[j] = (q0[ch[j]] - q3[ch[j]]) * s + q2[ch[j]];
            } else { sc[j] = 0.f; bi[j] = 0.f; }
        }
        float* yb = d_ybuf + (size_t)b * NN * CC2;
#pragma unroll
        for (int i = 0; i < 8; i++) {
            if (rows[i] >= M) continue;
#pragma unroll
            for (int j = 0; j < 8; j++)
                if (cols[j] < Nc) {
                    float t2 = acc[i][j] * sc[j] + bi[j];
                    yb[(size_t)rows[i] * CC2 + ch[j]] = t2 * normcdff(t2);
                }
        }
    } else { // MODE 4
        float sc[8], bi[8];
#pragma unroll
        for (int j = 0; j < 8; j++) {
            if (cols[j] < Nc) {
                float s = q1[cols[j]] * rsqrtf(q4[cols[j]] + BNEPS);
                sc[j] = s;
                bi[j] = (q0[cols[j]] - q3[cols[j]]) * s + q2[cols[j]];
            } else { sc[j] = 0.f; bi[j] = 0.f; }
        }
#pragma unroll
        for (int i = 0; i < 8; i++) {
            if (rows[i] >= M) continue;
#pragma unroll
            for (int j = 0; j < 8; j++)
                if (cols[j] < Nc)
                    d_obuf[(size_t)rows[i] * CC + cols[j]] = acc[i][j] * sc[j] + bi[j];
        }
    }
}

// ---------------- L2 normalize + sq + bf16 hi/lo concat buffers --------------
__global__ void norm_kernel() {
    int row = blockIdx.x;
    const float* hr = d_h + (size_t)row * CC;
    int t = threadIdx.x;                    // 64 threads
    float a0 = hr[t], a1 = hr[t + 64], a2 = hr[t + 128];
    float ss = a0 * a0 + a1 * a1 + a2 * a2;
#pragma unroll
    for (int o = 16; o > 0; o >>= 1) ss += __shfl_down_sync(0xffffffffu, ss, o);
    __shared__ float w1[2], w2[2];
    if ((t & 31) == 0) w1[t >> 5] = ss;
    __syncthreads();
    float norm = sqrtf(w1[0] + w1[1]);
    float inv = 1.0f / fmaxf(norm, 1e-12f);
    float xv[3] = { a0 * inv, a1 * inv, a2 * inv };
    float s2 = xv[0] * xv[0] + xv[1] * xv[1] + xv[2] * xv[2];
#pragma unroll
    for (int o = 16; o > 0; o >>= 1) s2 += __shfl_down_sync(0xffffffffu, s2, o);
    if ((t & 31) == 0) w2[t >> 5] = s2;

    __nv_bfloat16* xa = d_xa + (size_t)row * KTOT;
    __nv_bfloat16* xb = d_xb + (size_t)row * KTOT;
#pragma unroll
    for (int e = 0; e < 3; e++) {
        int c = t + e * 64;
        float x = xv[e];
        __nv_bfloat16 h = __float2bfloat16(x);
        __nv_bfloat16 l = __float2bfloat16(x - __bfloat162float(h));
        xa[c]       = h;  xa[192 + c] = h;  xa[384 + c] = l;
        xb[c]       = h;  xb[192 + c] = l;  xb[384 + c] = h;
    }
    __syncthreads();
    if (t == 0) d_sq[row] = w2[0] + w2[1];
}

// ---------------- dist via mma.sync bf16 (K=576 concat split) ----------------
// CTA 128x128, 4 warps 2x2, warp tile 64x64, K-slab 32, cp.async double-buffer.
// rel via 56x56 smem table; C staging stride 133 => conflict-free epilogue.
#define SROW 80                        // smem tile row bytes (40 bf16: 32 + 8 pad)
#define TILE_B (128 * SROW)            // 10240
#define SM_R   0                       // 12544 B
#define SM_IDX 12544                   // 2048 B (yyR,xxR,yyC,xxC int[128])
#define SM_BUF 14592
#define DS_STRIDE 133
#define DS_BYTES (128 * DS_STRIDE * 4) // 68096
#define DSM_TOTAL (SM_BUF + DS_BYTES)  // 82688 (> SM_BUF + 4*TILE_B = 55552)
__global__ void __launch_bounds__(128)
dist_mma_kernel() {
    if (blockIdx.y > blockIdx.x) return;
    extern __shared__ char smem[];
    const int tid = threadIdx.x, w = tid >> 5, lane = tid & 31;
    const int b = blockIdx.z;
    const int m0 = blockIdx.y * 128, n0 = blockIdx.x * 128;

    float* Rs  = reinterpret_cast<float*>(smem + SM_R);
    int*   yyR = reinterpret_cast<int*>(smem + SM_IDX);
    int*   xxR = yyR + 128;
    int*   yyC = yyR + 256;
    int*   xxC = yyR + 384;

    for (int i = tid; i < 56 * 56; i += 128) Rs[i] = d_R[i];
    {
        int rg = min(m0 + tid, NN - 1);
        yyR[tid] = rg / 56; xxR[tid] = rg - (rg / 56) * 56;
        int cg = min(n0 + tid, NN - 1);
        yyC[tid] = cg / 56; xxC[tid] = cg - (cg / 56) * 56;
    }

    const uint32_t sbuf = smem_u32(smem + SM_BUF);
    const uint32_t sAq[2] = { sbuf, sbuf + TILE_B };
    const uint32_t sBq[2] = { sbuf + 2 * TILE_B, sbuf + 3 * TILE_B };

    const __nv_bfloat16* baseA = d_xa + (size_t)b * NN * KTOT;
    const __nv_bfloat16* baseB = d_xb + (size_t)b * NN * KTOT;

    auto issue = [&](int s) {
        const int k0b = s * KSLAB * 2;
        const uint32_t dA = sAq[s & 1], dB = sBq[s & 1];
#pragma unroll
        for (int c = 0; c < 4; c++) {
            int ch = tid + c * 128;          // 0..511 = 128 rows x 4 chunks
            int row = ch >> 2, cg = (ch & 3) * 16;
            const char* ga = (const char*)(baseA + (size_t)min(m0 + row, NN - 1) * KTOT) + k0b + cg;
            const char* gb = (const char*)(baseB + (size_t)min(n0 + row, NN - 1) * KTOT) + k0b + cg;
            uint32_t off = row * SROW + cg;
            asm volatile("cp.async.cg.shared.global [%0], [%1], 16;" :: "r"(dA + off), "l"(ga));
            asm volatile("cp.async.cg.shared.global [%0], [%1], 16;" :: "r"(dB + off), "l"(gb));
        }
        asm volatile("cp.async.commit_group;" ::: "memory");
    };

    issue(0);
    issue(1);

    float acc[4][8][4];
#pragma unroll
    for (int i = 0; i < 4; i++)
#pragma unroll
        for (int j = 0; j < 8; j++)
#pragma unroll
            for (int k = 0; k < 4; k++) acc[i][j][k] = 0.0f;

    const int wm = w & 1;                         // rows wm*64
    const int wn = w >> 1;                        // cols wn*64
    const int aRow  = lane & 15;
    const int aColB = ((lane >> 4) * 8) * 2;
    const int bNr   = ((lane >> 4) << 3) + (lane & 7);
    const int bColB = (((lane >> 3) & 1) * 8) * 2;

    for (int s = 0; s < NSLABS; s++) {
        if (s < NSLABS - 1)
            asm volatile("cp.async.wait_group 1;" ::: "memory");
        else
            asm volatile("cp.async.wait_group 0;" ::: "memory");
        __syncthreads();
        const uint32_t cA = sAq[s & 1], cB = sBq[s & 1];
#pragma unroll
        for (int kk = 0; kk < 2; kk++) {
            const int k0b = kk * 32;
            uint32_t af[4][4];
#pragma unroll
            for (int mi = 0; mi < 4; mi++) {
                uint32_t addr = cA + (wm * 64 + mi * 16 + aRow) * SROW + k0b + aColB;
                asm volatile(
                    "ldmatrix.sync.aligned.m8n8.x4.shared.b16 {%0,%1,%2,%3}, [%4];"
                    : "=r"(af[mi][0]), "=r"(af[mi][1]), "=r"(af[mi][2]), "=r"(af[mi][3])
                    : "r"(addr));
            }
            uint32_t bfv[4][4];
#pragma unroll
            for (int nb = 0; nb < 4; nb++) {
                uint32_t addr = cB + (wn * 64 + nb * 16 + bNr) * SROW + k0b + bColB;
                asm volatile(
                    "ldmatrix.sync.aligned.m8n8.x4.shared.b16 {%0,%1,%2,%3}, [%4];"
                    : "=r"(bfv[nb][0]), "=r"(bfv[nb][1]), "=r"(bfv[nb][2]), "=r"(bfv[nb][3])
                    : "r"(addr));
            }
#pragma unroll
            for (int mi = 0; mi < 4; mi++)
#pragma unroll
                for (int ni = 0; ni < 8; ni++) {
                    uint32_t b0 = bfv[ni >> 1][(ni & 1) * 2 + 0];
                    uint32_t b1 = bfv[ni >> 1][(ni & 1) * 2 + 1];
                    asm volatile(
                        "mma.sync.aligned.m16n8k16.row.col.f32.bf16.bf16.f32 "
                        "{%0,%1,%2,%3}, {%4,%5,%6,%7}, {%8,%9}, {%0,%1,%2,%3};"
                        : "+f"(acc[mi][ni][0]), "+f"(acc[mi][ni][1]),
                          "+f"(acc[mi][ni][2]), "+f"(acc[mi][ni][3])
                        : "r"(af[mi][0]), "r"(af[mi][1]), "r"(af[mi][2]), "r"(af[mi][3]),
                          "r"(b0), "r"(b1));
                }
        }
        __syncthreads();
        if (s + 2 < NSLABS) issue(s + 2);
    }

    // ---- stage C to smem [128][133] (odd stride: conflict-free reads)
    float* Ds = reinterpret_cast<float*>(smem + SM_BUF);
#pragma unroll
    for (int mi = 0; mi < 4; mi++) {
        int r0 = wm * 64 + mi * 16 + (lane >> 2);
        int c0 = wn * 64 + (lane & 3) * 2;
#pragma unroll
        for (int ni = 0; ni < 8; ni++) {
            int cc = c0 + ni * 8;
            Ds[r0 * DS_STRIDE + cc]           = acc[mi][ni][0];
            Ds[r0 * DS_STRIDE + cc + 1]       = acc[mi][ni][1];
            Ds[(r0 + 8) * DS_STRIDE + cc]     = acc[mi][ni][2];
            Ds[(r0 + 8) * DS_STRIDE + cc + 1] = acc[mi][ni][3];
        }
    }
    __syncthreads();

    float* db = d_dist + (size_t)b * NN * NN;
    const float* sqb = d_sq + b * NN;

    // phase 1: mirror tile; lane = row (coalesced stores, conflict-free LDS)
    if (blockIdx.x != blockIdx.y) {
        for (int cl = w; cl < 128; cl += 4) {
            int m = n0 + cl;
            if (m >= NN) continue;
            float* dbm = db + (size_t)m * NN;
            const int yc = yyC[cl], xc = xxC[cl];
#pragma unroll
            for (int rq = 0; rq < 4; rq++) {
                int rl = rq * 32 + lane;
                int rg = m0 + rl;
                if (rg >= NN) continue;
                float v = Ds[rl * DS_STRIDE + cl];
                float relv = Rs[yyR[rl] * 56 + yc] + Rs[xxR[rl] * 56 + xc];
                dbm[rg] = sqb[rg] - 2.0f * v + relv;
            }
        }
    }

    // phase 2: normal tile; thread = column, sweep all 128 rows
    {
        const int c = tid;                 // 0..127
        const int gc = n0 + c;
        if (gc < NN) {
            const float sqc = sqb[gc];
            const int yc = yyC[c], xc = xxC[c];
#pragma unroll 1
            for (int rl = 0; rl < 128; rl++) {
                int rg = m0 + rl;
                if (rg >= NN) break;
                float v = Ds[rl * DS_STRIDE + c];
                float relv = Rs[yyR[rl] * 56 + yc] + Rs[xxR[rl] * 56 + xc];
                db[(size_t)rg * NN + gc] = sqc - 2.0f * v + relv;
            }
        }
    }
}

// ---------------- fused top-9 + gather/max-edge (4 rows per block) -----------
__global__ void __launch_bounds__(256) topk_gather_kernel() {
    const int r = threadIdx.x >> 6;          // 0..3 row within block
    const int g = threadIdx.x & 63;          // 0..63 lane within row group
    const int row = blockIdx.x * 4 + r;      // global row (b*N + n)
    const int b = row / NN, n = row % NN;
    const float4* dr4 = reinterpret_cast<const float4*>(
        d_dist + (size_t)b * NN * NN + (size_t)n * NN);

    float tv[KNB];
    int   ti[KNB];
#pragma unroll
    for (int q = 0; q < KNB; q++) { tv[q] = INFINITY; ti[q] = 0x7fffffff; }

    for (int i4 = g; i4 < NN / 4; i4 += 64) {
        float4 v4 = dr4[i4];
        const int mb = i4 * 4;
        float vv[4] = { v4.x, v4.y, v4.z, v4.w };
#pragma unroll
        for (int c = 0; c < 4; c++) {
            float v = vv[c];
            if (v < tv[KNB - 1]) {
                tv[KNB - 1] = v; ti[KNB - 1] = mb + c;
#pragma unroll
                for (int q = KNB - 1; q > 0; q--) {
                    if (tv[q] < tv[q - 1]) {
                        float fv = tv[q]; tv[q] = tv[q - 1]; tv[q - 1] = fv;
                        int   fi = ti[q]; ti[q] = ti[q - 1]; ti[q - 1] = fi;
                    }
                }
            }
        }
    }

    __shared__ float sv[256 * KNB];
    __shared__ int   si[256 * KNB];
#pragma unroll
    for (int q = 0; q < KNB; q++) {
        sv[threadIdx.x * KNB + q] = tv[q];
        si[threadIdx.x * KNB + q] = ti[q];
    }

    for (int stride = 32; stride >= 1; stride >>= 1) {
        __syncthreads();
        if (g < (unsigned)stride) {
            float* Av = &sv[(r * 64 + g) * KNB];
            int*   Ai = &si[(r * 64 + g) * KNB];
            float* Bv = &sv[(r * 64 + g + stride) * KNB];
            int*   Bi = &si[(r * 64 + g + stride) * KNB];
            float ov[KNB]; int oi[KNB];
            int ia = 0, ib = 0;
#pragma unroll
            for (int q = 0; q < KNB; q++) {
                float va = (ia < KNB) ? Av[ia] : INFINITY;
                float vb = (ib < KNB) ? Bv[ib] : INFINITY;
                int xa = (ia < KNB) ? Ai[ia] : 0x7fffffff;
                int xb = (ib < KNB) ? Bi[ib] : 0x7fffffff;
                bool takeA = (va < vb) || (va == vb && xa < xb);
                ov[q] = takeA ? va : vb;
                oi[q] = takeA ? xa : xb;
                if (takeA) ia++; else ib++;
            }
#pragma unroll
            for (int q = 0; q < KNB; q++) { Av[q] = ov[q]; Ai[q] = oi[q]; }
        }
    }
    __syncthreads();

    // ---- gather + max-edge: 64 threads per row, 3 channels each
    {
        const int* nn9 = &si[(r * 64) * KNB];
        const float* hb = d_h + (size_t)b * NN * CC;
        const float* hr = d_h + (size_t)row * CC;
        float* gb = d_gbuf + (size_t)row * CC2;
#pragma unroll
        for (int e = 0; e < 3; e++) {
            int c = g + e * 64;
            float hn = hr[c];
            float mx = -INFINITY;
#pragma unroll
            for (int j = 0; j < KNB; j++)
                mx = fmaxf(mx, hb[(size_t)nn9[j] * CC + c] - hn);
            gb[c]      = hn;
            gb[CC + c] = mx;
        }
    }
}

// ---------------- transpose (B,N,C)->(B,C,N) + residual ---------------------
__global__ void out_kernel(const float* __restrict__ x, float* __restrict__ out) {
    __shared__ float tile[32][33];
    const int b = blockIdx.z;
    const int n0 = blockIdx.x * 32, c0 = blockIdx.y * 32;
    const int tx = threadIdx.x, ty = threadIdx.y;
#pragma unroll
    for (int i = 0; i < 32; i += 8)
        tile[ty + i][tx] = d_obuf[((size_t)b * NN + n0 + ty + i) * CC + c0 + tx];
    __syncthreads();
#pragma unroll
    for (int i = 0; i < 32; i += 8) {
        int c = c0 + ty + i, n = n0 + tx;
        size_t o = ((size_t)b * CC + c) * NN + n;
        out[o] = tile[tx][ty + i] + x[o];
    }
}

// ---------------- launch ----------------------------------------------------
extern "C" void kernel_launch(void* const* d_in, const int* in_sizes, int n_in,
                              void* d_out, int out_size)
{
    (void)in_sizes; (void)n_in; (void)out_size;
    const float* x     = (const float*)d_in[0];
    const float* fc1_w = (const float*)d_in[1];
    const float* fc1_b = (const float*)d_in[2];
    const float* bn1_g = (const float*)d_in[3];
    const float* bn1_b = (const float*)d_in[4];
    const float* bn1_m = (const float*)d_in[5];
    const float* bn1_v = (const float*)d_in[6];
    const float* gc_w  = (const float*)d_in[7];
    const float* gc_b  = (const float*)d_in[8];
    const float* bng_g = (const float*)d_in[9];
    const float* bng_b = (const float*)d_in[10];
    const float* bng_m = (const float*)d_in[11];
    const float* bng_v = (const float*)d_in[12];
    const float* fc2_w = (const float*)d_in[13];
    const float* fc2_b = (const float*)d_in[14];
    const float* bn2_g = (const float*)d_in[15];
    const float* bn2_b = (const float*)d_in[16];
    const float* bn2_m = (const float*)d_in[17];
    const float* bn2_v = (const float*)d_in[18];
    float* out = (float*)d_out;

    cudaFuncSetAttribute(dist_mma_kernel,
                         cudaFuncAttributeMaxDynamicSharedMemorySize, DSM_TOTAL);

    // 1: rel position table (56x56)
    rel_table_kernel<<<25, 128>>>();
    // 2: fc1 + bn1 -> h
    gemm_kernel<0><<<dim3(2, 25, BB), 256>>>(x, fc1_w, fc1_b, bn1_g, bn1_b, bn1_m, bn1_v);
    // 3: normalize rows -> sq + bf16 concat split buffers
    norm_kernel<<<BB * NN, 64>>>();
    // 4: dist via mma.sync bf16 split (64x64 warp tiles)  [ncu capture slot]
    dist_mma_kernel<<<dim3(25, 25, BB), 128, DSM_TOTAL>>>();
    // 5: fused top-9 + gather/max-edge, 4 rows/block -> g = [h, d]
    topk_gather_kernel<<<BB * NN / 4, 256>>>();
    // 6: grouped conv + bn + gelu -> y
    gemm_kernel<3><<<dim3(1, 25, BB * 4), 256>>>(nullptr, gc_w, gc_b, bng_g, bng_b, bng_m, bng_v);
    // 7: fc2 + bn2 -> o
    gemm_kernel<4><<<dim3(2, 196, 1), 256>>>(nullptr, fc2_w, fc2_b, bn2_g, bn2_b, bn2_m, bn2_v);
    // 8: transpose + residual -> out
    out_kernel<<<dim3(98, 6, BB), dim3(32, 8)>>>(x, out);
}

// round 15
// speedup vs baseline: 1.0609x; 1.0609x over previous
#include <cuda_runtime.h>
#include <cuda_bf16.h>
#include <math.h>
#include <stdint.h>

// Problem constants (fixed shapes from setup_inputs)
#define BB  8
#define CC  192
#define HH  56
#define WW  56
#define NN  3136            // H*W
#define CC2 384             // 2*C
#define CG  96              // C2/4
#define KNB 9               // K_NEIGHBORS
#define BNEPS 1e-5f
#define KTOT 576            // 3*CC  (hi|hi|lo concat)
#define KSLAB 64
#define NSLABS 9            // KTOT/KSLAB

// ---------------- scratch (static device globals; no runtime alloc) --------
__device__ float d_R   [56 * 56];                          // rel position table
__device__ float d_h   [(size_t)BB * NN * CC];             // 19.3 MB
__device__ __nv_bfloat16 d_xa[(size_t)BB * NN * KTOT];     // 28.9 MB  [hi|hi|lo]
__device__ __nv_bfloat16 d_xb[(size_t)BB * NN * KTOT];     // 28.9 MB  [hi|lo|hi]
__device__ float d_sq  [BB * NN];
__device__ float d_dist[(size_t)BB * NN * NN];             // 314.7 MB
__device__ float d_gbuf[(size_t)BB * NN * CC2];            // 38.6 MB
__device__ float d_ybuf[(size_t)BB * NN * CC2];            // 38.6 MB

__device__ __forceinline__ uint32_t smem_u32(const void* p) {
    uint32_t a;
    asm("{ .reg .u64 t; cvta.to.shared.u64 t, %1; cvt.u32.u64 %0, t; }"
        : "=r"(a) : "l"(p));
    return a;
}

// ---------------- rel position table: R[a][b] = -2/C * emb(a).emb(b) --------
__global__ void rel_table_kernel() {
    int p = blockIdx.x * 128 + threadIdx.x;
    if (p >= 56 * 56) return;
    int a = p / 56, b = p - (p / 56) * 56;
    float s = 0.0f;
#pragma unroll 1
    for (int i = 0; i < 48; i++) {
        float wv = expf(-logf(10000.0f) * (float)i / 48.0f);
        float sa, ca, sb, cb;
        sincosf((float)a * wv, &sa, &ca);
        sincosf((float)b * wv, &sb, &cb);
        s += sa * sb + ca * cb;
    }
    d_R[p] = (-2.0f / (float)CC) * s;
}

// ---------------- 128x128x16 double-buffered SGEMM (modes 0,3,4) -----------
// MODE 0: fc1   A = x_b (K-major), bias+BN1 -> d_h
// MODE 3: group A = d_gbuf slice row-major, B = gc_w[g], bias+BN+GELU -> d_ybuf
// MODE 4: fc2   A = d_ybuf row-major, bias+BN2, transposed write + residual -> out
template <int MODE>
__global__ void __launch_bounds__(256, 2)
gemm_kernel(const float* __restrict__ Ain, const float* __restrict__ Bin,
            const float* __restrict__ q0, const float* __restrict__ q1,
            const float* __restrict__ q2, const float* __restrict__ q3,
            const float* __restrict__ q4,
            const float* __restrict__ xres, float* __restrict__ outp)
{
    constexpr bool AKM = (MODE == 0);     // A stored K-major

    int M, Nc, K, lda, ldb;
    const float* A;
    const float* B;
    const int bz = blockIdx.z;

    if (MODE == 0) {
        A = Ain + (size_t)bz * CC * NN;  B = Bin;
        M = NN; Nc = CC; K = CC; lda = NN; ldb = CC;
    } else if (MODE == 3) {
        int b = bz >> 2, g = bz & 3;
        A = d_gbuf + (size_t)b * NN * CC2 + g * CG;
        B = Bin + (size_t)g * CG * CG;
        M = NN; Nc = CG; K = CG; lda = CC2; ldb = CG;
    } else {
        A = d_ybuf; B = Bin;
        M = BB * NN; Nc = CC; K = CC2; lda = CC2; ldb = CC2;
    }

    __shared__ float As[2][16][128];
    __shared__ float Bs[2][16][128];

    const int tid = threadIdx.x;
    const int tx = tid & 15;
    const int ty = tid >> 4;
    const int m0 = blockIdx.y * 128;
    const int n0 = blockIdx.x * 128;

    const float* aptr0;
    const float* aptr1;
    int a_km_k = 0, a_km_m = 0;
    int a_rm_r = 0, a_rm_kq = 0;
    if (AKM) {
        a_km_k = tid >> 5;
        a_km_m = (tid & 31) * 4;
        int mc = min(m0 + a_km_m, M - 4);
        aptr0 = A + (size_t)a_km_k * lda + mc;
        aptr1 = A + (size_t)(a_km_k + 8) * lda + mc;
    } else {
        a_rm_r  = tid >> 1;
        a_rm_kq = (tid & 1) * 8;
        int rc = min(m0 + a_rm_r, M - 1);
        aptr0 = A + (size_t)rc * lda + a_rm_kq;
        aptr1 = aptr0 + 4;
    }
    const int b_rm_r  = tid >> 1;
    const int b_rm_kq = (tid & 1) * 8;
    const float* bptr0 = B + (size_t)min(n0 + b_rm_r, Nc - 1) * ldb + b_rm_kq;
    const float* bptr1 = bptr0 + 4;

    float4 ra0, ra1, rb0, rb1;
    ra0 = *reinterpret_cast<const float4*>(aptr0);
    ra1 = *reinterpret_cast<const float4*>(aptr1);
    rb0 = *reinterpret_cast<const float4*>(bptr0);
    rb1 = *reinterpret_cast<const float4*>(bptr1);
    if (AKM) {
        *reinterpret_cast<float4*>(&As[0][a_km_k][a_km_m])     = ra0;
        *reinterpret_cast<float4*>(&As[0][a_km_k + 8][a_km_m]) = ra1;
    } else {
        As[0][a_rm_kq + 0][a_rm_r] = ra0.x; As[0][a_rm_kq + 1][a_rm_r] = ra0.y;
        As[0][a_rm_kq + 2][a_rm_r] = ra0.z; As[0][a_rm_kq + 3][a_rm_r] = ra0.w;
        As[0][a_rm_kq + 4][a_rm_r] = ra1.x; As[0][a_rm_kq + 5][a_rm_r] = ra1.y;
        As[0][a_rm_kq + 6][a_rm_r] = ra1.z; As[0][a_rm_kq + 7][a_rm_r] = ra1.w;
    }
    Bs[0][b_rm_kq + 0][b_rm_r] = rb0.x; Bs[0][b_rm_kq + 1][b_rm_r] = rb0.y;
    Bs[0][b_rm_kq + 2][b_rm_r] = rb0.z; Bs[0][b_rm_kq + 3][b_rm_r] = rb0.w;
    Bs[0][b_rm_kq + 4][b_rm_r] = rb1.x; Bs[0][b_rm_kq + 5][b_rm_r] = rb1.y;
    Bs[0][b_rm_kq + 6][b_rm_r] = rb1.z; Bs[0][b_rm_kq + 7][b_rm_r] = rb1.w;
    __syncthreads();

    float acc[8][8];
#pragma unroll
    for (int i = 0; i < 8; i++)
#pragma unroll
        for (int j = 0; j < 8; j++) acc[i][j] = 0.0f;

    const int T = K >> 4;
    for (int t = 0; t < T; t++) {
        const int cur = t & 1;
        if (t + 1 < T) {
            if (AKM) { aptr0 += (size_t)16 * lda; aptr1 += (size_t)16 * lda; }
            else     { aptr0 += 16;               aptr1 += 16; }
            bptr0 += 16; bptr1 += 16;
            ra0 = *reinterpret_cast<const float4*>(aptr0);
            ra1 = *reinterpret_cast<const float4*>(aptr1);
            rb0 = *reinterpret_cast<const float4*>(bptr0);
            rb1 = *reinterpret_cast<const float4*>(bptr1);
        }
#pragma unroll
        for (int kk = 0; kk < 16; kk++) {
            float af[8], bf[8];
            *reinterpret_cast<float4*>(&af[0]) = *reinterpret_cast<const float4*>(&As[cur][kk][ty * 4]);
            *reinterpret_cast<float4*>(&af[4]) = *reinterpret_cast<const float4*>(&As[cur][kk][64 + ty * 4]);
            *reinterpret_cast<float4*>(&bf[0]) = *reinterpret_cast<const float4*>(&Bs[cur][kk][tx * 4]);
            *reinterpret_cast<float4*>(&bf[4]) = *reinterpret_cast<const float4*>(&Bs[cur][kk][64 + tx * 4]);
#pragma unroll
            for (int i = 0; i < 8; i++)
#pragma unroll
                for (int j = 0; j < 8; j++) acc[i][j] += af[i] * bf[j];
        }
        if (t + 1 < T) {
            const int nxt = cur ^ 1;
            if (AKM) {
                *reinterpret_cast<float4*>(&As[nxt][a_km_k][a_km_m])     = ra0;
                *reinterpret_cast<float4*>(&As[nxt][a_km_k + 8][a_km_m]) = ra1;
            } else {
                As[nxt][a_rm_kq + 0][a_rm_r] = ra0.x; As[nxt][a_rm_kq + 1][a_rm_r] = ra0.y;
                As[nxt][a_rm_kq + 2][a_rm_r] = ra0.z; As[nxt][a_rm_kq + 3][a_rm_r] = ra0.w;
                As[nxt][a_rm_kq + 4][a_rm_r] = ra1.x; As[nxt][a_rm_kq + 5][a_rm_r] = ra1.y;
                As[nxt][a_rm_kq + 6][a_rm_r] = ra1.z; As[nxt][a_rm_kq + 7][a_rm_r] = ra1.w;
            }
            Bs[nxt][b_rm_kq + 0][b_rm_r] = rb0.x; Bs[nxt][b_rm_kq + 1][b_rm_r] = rb0.y;
            Bs[nxt][b_rm_kq + 2][b_rm_r] = rb0.z; Bs[nxt][b_rm_kq + 3][b_rm_r] = rb0.w;
            Bs[nxt][b_rm_kq + 4][b_rm_r] = rb1.x; Bs[nxt][b_rm_kq + 5][b_rm_r] = rb1.y;
            Bs[nxt][b_rm_kq + 6][b_rm_r] = rb1.z; Bs[nxt][b_rm_kq + 7][b_rm_r] = rb1.w;
        }
        __syncthreads();
    }

    int rows[8], cols[8];
#pragma unroll
    for (int i = 0; i < 4; i++) {
        rows[i]     = m0 + ty * 4 + i;
        rows[i + 4] = m0 + 64 + ty * 4 + i;
        cols[i]     = n0 + tx * 4 + i;
        cols[i + 4] = n0 + 64 + tx * 4 + i;
    }

    if (MODE == 0) {
        float sc[8], bi[8];
#pragma unroll
        for (int j = 0; j < 8; j++) {
            if (cols[j] < Nc) {
                float s = q1[cols[j]] * rsqrtf(q4[cols[j]] + BNEPS);
                sc[j] = s;
                bi[j] = (q0[cols[j]] - q3[cols[j]]) * s + q2[cols[j]];
            } else { sc[j] = 0.f; bi[j] = 0.f; }
        }
        float* hb = d_h + (size_t)bz * NN * CC;
#pragma unroll
        for (int i = 0; i < 8; i++) {
            if (rows[i] >= M) continue;
#pragma unroll
            for (int j = 0; j < 8; j++)
                if (cols[j] < Nc)
                    hb[(size_t)rows[i] * CC + cols[j]] = acc[i][j] * sc[j] + bi[j];
        }
    } else if (MODE == 3) {
        int b = bz >> 2, g = bz & 3;
        float sc[8], bi[8];
        int ch[8];
#pragma unroll
        for (int j = 0; j < 8; j++) {
            ch[j] = g * CG + cols[j];
            if (cols[j] < Nc) {
                float s = q1[ch[j]] * rsqrtf(q4[ch[j]] + BNEPS);
                sc[j] = s;
                bi[j] = (q0[ch[j]] - q3[ch[j]]) * s + q2[ch[j]];
            } else { sc[j] = 0.f; bi[j] = 0.f; }
        }
        float* yb = d_ybuf + (size_t)b * NN * CC2;
#pragma unroll
        for (int i = 0; i < 8; i++) {
            if (rows[i] >= M) continue;
#pragma unroll
            for (int j = 0; j < 8; j++)
                if (cols[j] < Nc) {
                    float t2 = acc[i][j] * sc[j] + bi[j];
                    yb[(size_t)rows[i] * CC2 + ch[j]] = t2 * normcdff(t2);
                }
        }
    } else { // MODE 4: fc2 + BN2, transposed write + residual -> out
        float sc[8], bi[8];
#pragma unroll
        for (int j = 0; j < 8; j++) {
            if (cols[j] < Nc) {
                float s = q1[cols[j]] * rsqrtf(q4[cols[j]] + BNEPS);
                sc[j] = s;
                bi[j] = (q0[cols[j]] - q3[cols[j]]) * s + q2[cols[j]];
            } else { sc[j] = 0.f; bi[j] = 0.f; }
        }
        // out[(b*CC + col)*NN + n] = acc*sc + bi + x[same]
#pragma unroll
        for (int half = 0; half < 2; half++) {
            const int i0 = half * 4;
            // all rows valid here (M = BB*NN divides grid exactly)
            const int bq0 = rows[i0] / NN;
            const int bq3 = rows[i0 + 3] / NN;
            const int nq0 = rows[i0] - bq0 * NN;
            const bool fast = (bq0 == bq3);   // 4-row group within one batch
#pragma unroll
            for (int j = 0; j < 8; j++) {
                if (cols[j] >= Nc) continue;
                if (fast) {
                    size_t o = ((size_t)bq0 * CC + cols[j]) * NN + nq0;
                    float4 xv = *reinterpret_cast<const float4*>(&xres[o]);
                    float4 v;
                    v.x = acc[i0 + 0][j] * sc[j] + bi[j] + xv.x;
                    v.y = acc[i0 + 1][j] * sc[j] + bi[j] + xv.y;
                    v.z = acc[i0 + 2][j] * sc[j] + bi[j] + xv.z;
                    v.w = acc[i0 + 3][j] * sc[j] + bi[j] + xv.w;
                    *reinterpret_cast<float4*>(&outp[o]) = v;
                } else {
#pragma unroll
                    for (int i = 0; i < 4; i++) {
                        int rg = rows[i0 + i];
                        int bq = rg / NN, nq = rg - bq * NN;
                        size_t o = ((size_t)bq * CC + cols[j]) * NN + nq;
                        outp[o] = acc[i0 + i][j] * sc[j] + bi[j] + xres[o];
                    }
                }
            }
        }
    }
}

// ---------------- L2 normalize + sq + bf16 hi/lo concat buffers --------------
__global__ void norm_kernel() {
    int row = blockIdx.x;
    const float* hr = d_h + (size_t)row * CC;
    int t = threadIdx.x;                    // 64 threads
    float a0 = hr[t], a1 = hr[t + 64], a2 = hr[t + 128];
    float ss = a0 * a0 + a1 * a1 + a2 * a2;
#pragma unroll
    for (int o = 16; o > 0; o >>= 1) ss += __shfl_down_sync(0xffffffffu, ss, o);
    __shared__ float w1[2], w2[2];
    if ((t & 31) == 0) w1[t >> 5] = ss;
    __syncthreads();
    float norm = sqrtf(w1[0] + w1[1]);
    float inv = 1.0f / fmaxf(norm, 1e-12f);
    float xv[3] = { a0 * inv, a1 * inv, a2 * inv };
    float s2 = xv[0] * xv[0] + xv[1] * xv[1] + xv[2] * xv[2];
#pragma unroll
    for (int o = 16; o > 0; o >>= 1) s2 += __shfl_down_sync(0xffffffffu, s2, o);
    if ((t & 31) == 0) w2[t >> 5] = s2;

    __nv_bfloat16* xa = d_xa + (size_t)row * KTOT;
    __nv_bfloat16* xb = d_xb + (size_t)row * KTOT;
#pragma unroll
    for (int e = 0; e < 3; e++) {
        int c = t + e * 64;
        float x = xv[e];
        __nv_bfloat16 h = __float2bfloat16(x);
        __nv_bfloat16 l = __float2bfloat16(x - __bfloat162float(h));
        xa[c]       = h;  xa[192 + c] = h;  xa[384 + c] = l;
        xb[c]       = h;  xb[192 + c] = l;  xb[384 + c] = h;
    }
    __syncthreads();
    if (t == 0) d_sq[row] = w2[0] + w2[1];
}

// ---------------- dist via mma.sync bf16 (K=576 concat split) ----------------
// CTA 128x128, 8 warps 4(m)x2(n), warp tile 32x64, K-slab 64, cp.async dbl-buf.
// rel via 56x56 smem table; C staging stride 133 (odd) => conflict-free epilogue.
#define SROW 144                       // smem tile row bytes (72 bf16: 64 + 8 pad)
#define TILE_B (128 * SROW)            // 18432
#define SM_R   0                       // 12544 B
#define SM_IDX 12544                   // 2048 B (yyR,xxR,yyC,xxC int[128])
#define SM_BUF 14592
#define DS_STRIDE 133
#define DSM_TOTAL (SM_BUF + 4 * TILE_B)   // 88320 (>= SM_BUF + 128*133*4)
__global__ void __launch_bounds__(256)
dist_mma_kernel() {
    if (blockIdx.y > blockIdx.x) return;
    extern __shared__ char smem[];
    const int tid = threadIdx.x, w = tid >> 5, lane = tid & 31;
    const int b = blockIdx.z;
    const int m0 = blockIdx.y * 128, n0 = blockIdx.x * 128;

    float* Rs  = reinterpret_cast<float*>(smem + SM_R);
    int*   yyR = reinterpret_cast<int*>(smem + SM_IDX);
    int*   xxR = yyR + 128;
    int*   yyC = yyR + 256;
    int*   xxC = yyR + 384;

    for (int i = tid; i < 56 * 56; i += 256) Rs[i] = d_R[i];
    if (tid < 128) {
        int rg = min(m0 + tid, NN - 1);
        yyR[tid] = rg / 56; xxR[tid] = rg - (rg / 56) * 56;
        int cg = min(n0 + tid, NN - 1);
        yyC[tid] = cg / 56; xxC[tid] = cg - (cg / 56) * 56;
    }

    const uint32_t sbuf = smem_u32(smem + SM_BUF);
    const uint32_t sAq[2] = { sbuf, sbuf + TILE_B };
    const uint32_t sBq[2] = { sbuf + 2 * TILE_B, sbuf + 3 * TILE_B };

    const __nv_bfloat16* baseA = d_xa + (size_t)b * NN * KTOT;
    const __nv_bfloat16* baseB = d_xb + (size_t)b * NN * KTOT;

    auto issue = [&](int s) {
        const int k0b = s * KSLAB * 2;
        const uint32_t dA = sAq[s & 1], dB = sBq[s & 1];
#pragma unroll
        for (int c = 0; c < 4; c++) {
            int ch = tid + c * 256;
            int row = ch >> 3, cg = (ch & 7) * 16;
            const char* ga = (const char*)(baseA + (size_t)min(m0 + row, NN - 1) * KTOT) + k0b + cg;
            const char* gb = (const char*)(baseB + (size_t)min(n0 + row, NN - 1) * KTOT) + k0b + cg;
            uint32_t off = row * SROW + cg;
            asm volatile("cp.async.cg.shared.global [%0], [%1], 16;" :: "r"(dA + off), "l"(ga));
            asm volatile("cp.async.cg.shared.global [%0], [%1], 16;" :: "r"(dB + off), "l"(gb));
        }
        asm volatile("cp.async.commit_group;" ::: "memory");
    };

    issue(0);
    issue(1);

    float acc[2][8][4];
#pragma unroll
    for (int i = 0; i < 2; i++)
#pragma unroll
        for (int j = 0; j < 8; j++)
#pragma unroll
            for (int k = 0; k < 4; k++) acc[i][j][k] = 0.0f;

    const int wm = w & 3;                         // rows wm*32
    const int wn = w >> 2;                        // cols wn*64
    const int aRow  = lane & 15;
    const int aColB = ((lane >> 4) * 8) * 2;
    const int bNr   = ((lane >> 4) << 3) + (lane & 7);
    const int bColB = (((lane >> 3) & 1) * 8) * 2;

    for (int s = 0; s < NSLABS; s++) {
        if (s < NSLABS - 1)
            asm volatile("cp.async.wait_group 1;" ::: "memory");
        else
            asm volatile("cp.async.wait_group 0;" ::: "memory");
        __syncthreads();
        const uint32_t cA = sAq[s & 1], cB = sBq[s & 1];
#pragma unroll
        for (int kk = 0; kk < 4; kk++) {
            const int k0b = kk * 32;
            uint32_t af[2][4];
#pragma unroll
            for (int mi = 0; mi < 2; mi++) {
                uint32_t addr = cA + (wm * 32 + mi * 16 + aRow) * SROW + k0b + aColB;
                asm volatile(
                    "ldmatrix.sync.aligned.m8n8.x4.shared.b16 {%0,%1,%2,%3}, [%4];"
                    : "=r"(af[mi][0]), "=r"(af[mi][1]), "=r"(af[mi][2]), "=r"(af[mi][3])
                    : "r"(addr));
            }
            uint32_t bfv[4][4];
#pragma unroll
            for (int nb = 0; nb < 4; nb++) {
                uint32_t addr = cB + (wn * 64 + nb * 16 + bNr) * SROW + k0b + bColB;
                asm volatile(
                    "ldmatrix.sync.aligned.m8n8.x4.shared.b16 {%0,%1,%2,%3}, [%4];"
                    : "=r"(bfv[nb][0]), "=r"(bfv[nb][1]), "=r"(bfv[nb][2]), "=r"(bfv[nb][3])
                    : "r"(addr));
            }
#pragma unroll
            for (int mi = 0; mi < 2; mi++)
#pragma unroll
                for (int ni = 0; ni < 8; ni++) {
                    uint32_t b0 = bfv[ni >> 1][(ni & 1) * 2 + 0];
                    uint32_t b1 = bfv[ni >> 1][(ni & 1) * 2 + 1];
                    asm volatile(
                        "mma.sync.aligned.m16n8k16.row.col.f32.bf16.bf16.f32 "
                        "{%0,%1,%2,%3}, {%4,%5,%6,%7}, {%8,%9}, {%0,%1,%2,%3};"
                        : "+f"(acc[mi][ni][0]), "+f"(acc[mi][ni][1]),
                          "+f"(acc[mi][ni][2]), "+f"(acc[mi][ni][3])
                        : "r"(af[mi][0]), "r"(af[mi][1]), "r"(af[mi][2]), "r"(af[mi][3]),
                          "r"(b0), "r"(b1));
                }
        }
        __syncthreads();
        if (s + 2 < NSLABS) issue(s + 2);
    }

    // ---- stage C to smem [128][DS_STRIDE=133] (odd stride: conflict-free reads)
    float* Ds = reinterpret_cast<float*>(smem + SM_BUF);
#pragma unroll
    for (int mi = 0; mi < 2; mi++) {
        int r0 = wm * 32 + mi * 16 + (lane >> 2);
        int c0 = wn * 64 + (lane & 3) * 2;
#pragma unroll
        for (int ni = 0; ni < 8; ni++) {
            int cc = c0 + ni * 8;
            Ds[r0 * DS_STRIDE + cc]           = acc[mi][ni][0];
            Ds[r0 * DS_STRIDE + cc + 1]       = acc[mi][ni][1];
            Ds[(r0 + 8) * DS_STRIDE + cc]     = acc[mi][ni][2];
            Ds[(r0 + 8) * DS_STRIDE + cc + 1] = acc[mi][ni][3];
        }
    }
    __syncthreads();

    float* db = d_dist + (size_t)b * NN * NN;
    const float* sqb = d_sq + b * NN;

    // phase 1: mirror tile; lane = row (coalesced stores, conflict-free LDS)
    if (blockIdx.x != blockIdx.y) {
        for (int cl = w; cl < 128; cl += 8) {
            int m = n0 + cl;
            if (m >= NN) continue;
            float* dbm = db + (size_t)m * NN;
            const int yc = yyC[cl], xc = xxC[cl];
#pragma unroll
            for (int rq = 0; rq < 4; rq++) {
                int rl = rq * 32 + lane;
                int rg = m0 + rl;
                if (rg >= NN) continue;
                float v = Ds[rl * DS_STRIDE + cl];
                float relv = Rs[yyR[rl] * 56 + yc] + Rs[xxR[rl] * 56 + xc];
                dbm[rg] = sqb[rg] - 2.0f * v + relv;
            }
        }
    }

    // phase 2: normal tile; thread = column, sweep rows
    {
        const int c = tid & 127;
        const int rh = (tid >> 7) * 64;
        const int gc = n0 + c;
        if (gc < NN) {
            const float sqc = sqb[gc];
            const int yc = yyC[c], xc = xxC[c];
#pragma unroll 1
            for (int r = 0; r < 64; r++) {
                int rl = rh + r;
                int rg = m0 + rl;
                if (rg >= NN) break;
                float v = Ds[rl * DS_STRIDE + c];
                float relv = Rs[yyR[rl] * 56 + yc] + Rs[xxR[rl] * 56 + xc];
                db[(size_t)rg * NN + gc] = sqc - 2.0f * v + relv;
            }
        }
    }
}

// ---------------- fused top-9 + gather/max-edge (4 rows per block) -----------
__global__ void __launch_bounds__(256) topk_gather_kernel() {
    const int r = threadIdx.x >> 6;          // 0..3 row within block
    const int g = threadIdx.x & 63;          // 0..63 lane within row group
    const int row = blockIdx.x * 4 + r;      // global row (b*N + n)
    const int b = row / NN, n = row % NN;
    const float4* dr4 = reinterpret_cast<const float4*>(
        d_dist + (size_t)b * NN * NN + (size_t)n * NN);

    float tv[KNB];
    int   ti[KNB];
#pragma unroll
    for (int q = 0; q < KNB; q++) { tv[q] = INFINITY; ti[q] = 0x7fffffff; }

    for (int i4 = g; i4 < NN / 4; i4 += 64) {
        float4 v4 = dr4[i4];
        const int mb = i4 * 4;
        float vv[4] = { v4.x, v4.y, v4.z, v4.w };
#pragma unroll
        for (int c = 0; c < 4; c++) {
            float v = vv[c];
            if (v < tv[KNB - 1]) {
                tv[KNB - 1] = v; ti[KNB - 1] = mb + c;
#pragma unroll
                for (int q = KNB - 1; q > 0; q--) {
                    if (tv[q] < tv[q - 1]) {
                        float fv = tv[q]; tv[q] = tv[q - 1]; tv[q - 1] = fv;
                        int   fi = ti[q]; ti[q] = ti[q - 1]; ti[q - 1] = fi;
                    }
                }
            }
        }
    }

    __shared__ float sv[256 * KNB];
    __shared__ int   si[256 * KNB];
#pragma unroll
    for (int q = 0; q < KNB; q++) {
        sv[threadIdx.x * KNB + q] = tv[q];
        si[threadIdx.x * KNB + q] = ti[q];
    }

    for (int stride = 32; stride >= 1; stride >>= 1) {
        __syncthreads();
        if (g < (unsigned)stride) {
            float* Av = &sv[(r * 64 + g) * KNB];
            int*   Ai = &si[(r * 64 + g) * KNB];
            float* Bv = &sv[(r * 64 + g + stride) * KNB];
            int*   Bi = &si[(r * 64 + g + stride) * KNB];
            float ov[KNB]; int oi[KNB];
            int ia = 0, ib = 0;
#pragma unroll
            for (int q = 0; q < KNB; q++) {
                float va = (ia < KNB) ? Av[ia] : INFINITY;
                float vb = (ib < KNB) ? Bv[ib] : INFINITY;
                int xa = (ia < KNB) ? Ai[ia] : 0x7fffffff;
                int xb = (ib < KNB) ? Bi[ib] : 0x7fffffff;
                bool takeA = (va < vb) || (va == vb && xa < xb);
                ov[q] = takeA ? va : vb;
                oi[q] = takeA ? xa : xb;
                if (takeA) ia++; else ib++;
            }
#pragma unroll
            for (int q = 0; q < KNB; q++) { Av[q] = ov[q]; Ai[q] = oi[q]; }
        }
    }
    __syncthreads();

    // ---- gather + max-edge: 64 threads per row, 3 channels each
    {
        const int* nn9 = &si[(r * 64) * KNB];
        const float* hb = d_h + (size_t)b * NN * CC;
        const float* hr = d_h + (size_t)row * CC;
        float* gb = d_gbuf + (size_t)row * CC2;
#pragma unroll
        for (int e = 0; e < 3; e++) {
            int c = g + e * 64;
            float hn = hr[c];
            float mx = -INFINITY;
#pragma unroll
            for (int j = 0; j < KNB; j++)
                mx = fmaxf(mx, hb[(size_t)nn9[j] * CC + c] - hn);
            gb[c]      = hn;
            gb[CC + c] = mx;
        }
    }
}

// ---------------- launch ----------------------------------------------------
extern "C" void kernel_launch(void* const* d_in, const int* in_sizes, int n_in,
                              void* d_out, int out_size)
{
    (void)in_sizes; (void)n_in; (void)out_size;
    const float* x     = (const float*)d_in[0];
    const float* fc1_w = (const float*)d_in[1];
    const float* fc1_b = (const float*)d_in[2];
    const float* bn1_g = (const float*)d_in[3];
    const float* bn1_b = (const float*)d_in[4];
    const float* bn1_m = (const float*)d_in[5];
    const float* bn1_v = (const float*)d_in[6];
    const float* gc_w  = (const float*)d_in[7];
    const float* gc_b  = (const float*)d_in[8];
    const float* bng_g = (const float*)d_in[9];
    const float* bng_b = (const float*)d_in[10];
    const float* bng_m = (const float*)d_in[11];
    const float* bng_v = (const float*)d_in[12];
    const float* fc2_w = (const float*)d_in[13];
    const float* fc2_b = (const float*)d_in[14];
    const float* bn2_g = (const float*)d_in[15];
    const float* bn2_b = (const float*)d_in[16];
    const float* bn2_m = (const float*)d_in[17];
    const float* bn2_v = (const float*)d_in[18];
    float* out = (float*)d_out;

    cudaFuncSetAttribute(dist_mma_kernel,
                         cudaFuncAttributeMaxDynamicSharedMemorySize, DSM_TOTAL);

    // 1: rel position table (56x56)
    rel_table_kernel<<<25, 128>>>();
    // 2: fc1 + bn1 -> h
    gemm_kernel<0><<<dim3(2, 25, BB), 256>>>(x, fc1_w, fc1_b, bn1_g, bn1_b, bn1_m, bn1_v, nullptr, nullptr);
    // 3: normalize rows -> sq + bf16 concat split buffers
    norm_kernel<<<BB * NN, 64>>>();
    // 4: dist via mma.sync bf16 split (round-13 config)  [ncu capture slot]
    dist_mma_kernel<<<dim3(25, 25, BB), 256, DSM_TOTAL>>>();
    // 5: fused top-9 + gather/max-edge, 4 rows/block -> g = [h, d]
    topk_gather_kernel<<<BB * NN / 4, 256>>>();
    // 6: grouped conv + bn + gelu -> y
    gemm_kernel<3><<<dim3(1, 25, BB * 4), 256>>>(nullptr, gc_w, gc_b, bng_g, bng_b, bng_m, bng_v, nullptr, nullptr);
    // 7: fc2 + bn2 + transpose + residual -> out (fused epilogue)
    gemm_kernel<4><<<dim3(2, 196, 1), 256>>>(nullptr, fc2_w, fc2_b, bn2_g, bn2_b, bn2_m, bn2_v, x, out);
}

// round 16
// speedup vs baseline: 1.0934x; 1.0307x over previous
#include <cuda_runtime.h>
#include <cuda_bf16.h>
#include <math.h>
#include <stdint.h>

// Problem constants (fixed shapes from setup_inputs)
#define BB  8
#define CC  192
#define HH  56
#define WW  56
#define NN  3136            // H*W
#define CC2 384             // 2*C
#define CG  96              // C2/4
#define KNB 9               // K_NEIGHBORS
#define BNEPS 1e-5f
#define KTOT 576            // 3*CC  (hi|hi|lo concat)  -- dist
#define KSLAB 64
#define NSLABS 9            // KTOT/KSLAB
#define FKTOT 1152          // 3*CC2 (split concat)     -- fc2
#define FNSLABS 18          // FKTOT/KSLAB
#define MTOT (BB * NN)      // 25088

// ---------------- scratch (static device globals; no runtime alloc) --------
__device__ float d_R   [56 * 56];                          // rel position table
__device__ float d_h   [(size_t)BB * NN * CC];             // 19.3 MB
__device__ __nv_bfloat16 d_xa[(size_t)BB * NN * KTOT];     // 28.9 MB  [hi|hi|lo]
__device__ __nv_bfloat16 d_xb[(size_t)BB * NN * KTOT];     // 28.9 MB  [hi|lo|hi]
__device__ float d_sq  [BB * NN];
__device__ float d_dist[(size_t)BB * NN * NN];             // 314.7 MB
__device__ float d_gbuf[(size_t)BB * NN * CC2];            // 38.6 MB
__device__ __nv_bfloat16 d_ya[(size_t)MTOT * FKTOT];       // 57.8 MB  [yh|yh|yl]
__device__ __nv_bfloat16 d_wb[CC * FKTOT];                 // 0.44 MB  [wh|wl|wh]

__device__ __forceinline__ uint32_t smem_u32(const void* p) {
    uint32_t a;
    asm("{ .reg .u64 t; cvta.to.shared.u64 t, %1; cvt.u32.u64 %0, t; }"
        : "=r"(a) : "l"(p));
    return a;
}

// ---------------- rel position table: R[a][b] = -2/C * emb(a).emb(b) --------
__global__ void rel_table_kernel() {
    int p = blockIdx.x * 128 + threadIdx.x;
    if (p >= 56 * 56) return;
    int a = p / 56, b = p - (p / 56) * 56;
    float s = 0.0f;
#pragma unroll 1
    for (int i = 0; i < 48; i++) {
        float wv = expf(-logf(10000.0f) * (float)i / 48.0f);
        float sa, ca, sb, cb;
        sincosf((float)a * wv, &sa, &ca);
        sincosf((float)b * wv, &sb, &cb);
        s += sa * sb + ca * cb;
    }
    d_R[p] = (-2.0f / (float)CC) * s;
}

// ---------------- split fc2_w into bf16 concat [wh|wl|wh] --------------------
__global__ void wsplit_kernel(const float* __restrict__ w) {
    int i = blockIdx.x * 256 + threadIdx.x;       // 192*384
    if (i >= CC * CC2) return;
    int d = i / CC2, k = i - (i / CC2) * CC2;
    float v = w[i];
    __nv_bfloat16 h = __float2bfloat16(v);
    __nv_bfloat16 l = __float2bfloat16(v - __bfloat162float(h));
    __nv_bfloat16* row = d_wb + (size_t)d * FKTOT;
    row[k] = h; row[CC2 + k] = l; row[2 * CC2 + k] = h;
}

// ---------------- 128x128x16 double-buffered SGEMM (modes 0,3) --------------
// MODE 0: fc1   A = x_b (K-major), bias+BN1 -> d_h
// MODE 3: group A = d_gbuf slice, B = gc_w[g], bias+BN+GELU -> d_ya (bf16 split)
template <int MODE>
__global__ void __launch_bounds__(256, 2)
gemm_kernel(const float* __restrict__ Ain, const float* __restrict__ Bin,
            const float* __restrict__ q0, const float* __restrict__ q1,
            const float* __restrict__ q2, const float* __restrict__ q3,
            const float* __restrict__ q4)
{
    constexpr bool AKM = (MODE == 0);     // A stored K-major

    int M, Nc, K, lda, ldb;
    const float* A;
    const float* B;
    const int bz = blockIdx.z;

    if (MODE == 0) {
        A = Ain + (size_t)bz * CC * NN;  B = Bin;
        M = NN; Nc = CC; K = CC; lda = NN; ldb = CC;
    } else {                   // MODE 3
        int b = bz >> 2, g = bz & 3;
        A = d_gbuf + (size_t)b * NN * CC2 + g * CG;
        B = Bin + (size_t)g * CG * CG;
        M = NN; Nc = CG; K = CG; lda = CC2; ldb = CG;
    }

    __shared__ float As[2][16][128];
    __shared__ float Bs[2][16][128];

    const int tid = threadIdx.x;
    const int tx = tid & 15;
    const int ty = tid >> 4;
    const int m0 = blockIdx.y * 128;
    const int n0 = blockIdx.x * 128;

    const float* aptr0;
    const float* aptr1;
    int a_km_k = 0, a_km_m = 0;
    int a_rm_r = 0, a_rm_kq = 0;
    if (AKM) {
        a_km_k = tid >> 5;
        a_km_m = (tid & 31) * 4;
        int mc = min(m0 + a_km_m, M - 4);
        aptr0 = A + (size_t)a_km_k * lda + mc;
        aptr1 = A + (size_t)(a_km_k + 8) * lda + mc;
    } else {
        a_rm_r  = tid >> 1;
        a_rm_kq = (tid & 1) * 8;
        int rc = min(m0 + a_rm_r, M - 1);
        aptr0 = A + (size_t)rc * lda + a_rm_kq;
        aptr1 = aptr0 + 4;
    }
    const int b_rm_r  = tid >> 1;
    const int b_rm_kq = (tid & 1) * 8;
    const float* bptr0 = B + (size_t)min(n0 + b_rm_r, Nc - 1) * ldb + b_rm_kq;
    const float* bptr1 = bptr0 + 4;

    float4 ra0, ra1, rb0, rb1;
    ra0 = *reinterpret_cast<const float4*>(aptr0);
    ra1 = *reinterpret_cast<const float4*>(aptr1);
    rb0 = *reinterpret_cast<const float4*>(bptr0);
    rb1 = *reinterpret_cast<const float4*>(bptr1);
    if (AKM) {
        *reinterpret_cast<float4*>(&As[0][a_km_k][a_km_m])     = ra0;
        *reinterpret_cast<float4*>(&As[0][a_km_k + 8][a_km_m]) = ra1;
    } else {
        As[0][a_rm_kq + 0][a_rm_r] = ra0.x; As[0][a_rm_kq + 1][a_rm_r] = ra0.y;
        As[0][a_rm_kq + 2][a_rm_r] = ra0.z; As[0][a_rm_kq + 3][a_rm_r] = ra0.w;
        As[0][a_rm_kq + 4][a_rm_r] = ra1.x; As[0][a_rm_kq + 5][a_rm_r] = ra1.y;
        As[0][a_rm_kq + 6][a_rm_r] = ra1.z; As[0][a_rm_kq + 7][a_rm_r] = ra1.w;
    }
    Bs[0][b_rm_kq + 0][b_rm_r] = rb0.x; Bs[0][b_rm_kq + 1][b_rm_r] = rb0.y;
    Bs[0][b_rm_kq + 2][b_rm_r] = rb0.z; Bs[0][b_rm_kq + 3][b_rm_r] = rb0.w;
    Bs[0][b_rm_kq + 4][b_rm_r] = rb1.x; Bs[0][b_rm_kq + 5][b_rm_r] = rb1.y;
    Bs[0][b_rm_kq + 6][b_rm_r] = rb1.z; Bs[0][b_rm_kq + 7][b_rm_r] = rb1.w;
    __syncthreads();

    float acc[8][8];
#pragma unroll
    for (int i = 0; i < 8; i++)
#pragma unroll
        for (int j = 0; j < 8; j++) acc[i][j] = 0.0f;

    const int T = K >> 4;
    for (int t = 0; t < T; t++) {
        const int cur = t & 1;
        if (t + 1 < T) {
            if (AKM) { aptr0 += (size_t)16 * lda; aptr1 += (size_t)16 * lda; }
            else     { aptr0 += 16;               aptr1 += 16; }
            bptr0 += 16; bptr1 += 16;
            ra0 = *reinterpret_cast<const float4*>(aptr0);
            ra1 = *reinterpret_cast<const float4*>(aptr1);
            rb0 = *reinterpret_cast<const float4*>(bptr0);
            rb1 = *reinterpret_cast<const float4*>(bptr1);
        }
#pragma unroll
        for (int kk = 0; kk < 16; kk++) {
            float af[8], bf[8];
            *reinterpret_cast<float4*>(&af[0]) = *reinterpret_cast<const float4*>(&As[cur][kk][ty * 4]);
            *reinterpret_cast<float4*>(&af[4]) = *reinterpret_cast<const float4*>(&As[cur][kk][64 + ty * 4]);
            *reinterpret_cast<float4*>(&bf[0]) = *reinterpret_cast<const float4*>(&Bs[cur][kk][tx * 4]);
            *reinterpret_cast<float4*>(&bf[4]) = *reinterpret_cast<const float4*>(&Bs[cur][kk][64 + tx * 4]);
#pragma unroll
            for (int i = 0; i < 8; i++)
#pragma unroll
                for (int j = 0; j < 8; j++) acc[i][j] += af[i] * bf[j];
        }
        if (t + 1 < T) {
            const int nxt = cur ^ 1;
            if (AKM) {
                *reinterpret_cast<float4*>(&As[nxt][a_km_k][a_km_m])     = ra0;
                *reinterpret_cast<float4*>(&As[nxt][a_km_k + 8][a_km_m]) = ra1;
            } else {
                As[nxt][a_rm_kq + 0][a_rm_r] = ra0.x; As[nxt][a_rm_kq + 1][a_rm_r] = ra0.y;
                As[nxt][a_rm_kq + 2][a_rm_r] = ra0.z; As[nxt][a_rm_kq + 3][a_rm_r] = ra0.w;
                As[nxt][a_rm_kq + 4][a_rm_r] = ra1.x; As[nxt][a_rm_kq + 5][a_rm_r] = ra1.y;
                As[nxt][a_rm_kq + 6][a_rm_r] = ra1.z; As[nxt][a_rm_kq + 7][a_rm_r] = ra1.w;
            }
            Bs[nxt][b_rm_kq + 0][b_rm_r] = rb0.x; Bs[nxt][b_rm_kq + 1][b_rm_r] = rb0.y;
            Bs[nxt][b_rm_kq + 2][b_rm_r] = rb0.z; Bs[nxt][b_rm_kq + 3][b_rm_r] = rb0.w;
            Bs[nxt][b_rm_kq + 4][b_rm_r] = rb1.x; Bs[nxt][b_rm_kq + 5][b_rm_r] = rb1.y;
            Bs[nxt][b_rm_kq + 6][b_rm_r] = rb1.z; Bs[nxt][b_rm_kq + 7][b_rm_r] = rb1.w;
        }
        __syncthreads();
    }

    int rows[8], cols[8];
#pragma unroll
    for (int i = 0; i < 4; i++) {
        rows[i]     = m0 + ty * 4 + i;
        rows[i + 4] = m0 + 64 + ty * 4 + i;
        cols[i]     = n0 + tx * 4 + i;
        cols[i + 4] = n0 + 64 + tx * 4 + i;
    }

    if (MODE == 0) {
        float sc[8], bi[8];
#pragma unroll
        for (int j = 0; j < 8; j++) {
            if (cols[j] < Nc) {
                float s = q1[cols[j]] * rsqrtf(q4[cols[j]] + BNEPS);
                sc[j] = s;
                bi[j] = (q0[cols[j]] - q3[cols[j]]) * s + q2[cols[j]];
            } else { sc[j] = 0.f; bi[j] = 0.f; }
        }
        float* hb = d_h + (size_t)bz * NN * CC;
#pragma unroll
        for (int i = 0; i < 8; i++) {
            if (rows[i] >= M) continue;
#pragma unroll
            for (int j = 0; j < 8; j++)
                if (cols[j] < Nc)
                    hb[(size_t)rows[i] * CC + cols[j]] = acc[i][j] * sc[j] + bi[j];
        }
    } else { // MODE 3: gelu(BN(y)) -> d_ya in split concat bf16 [yh|yh|yl]
        int b = bz >> 2, g = bz & 3;
        float sc[8], bi[8];
        int ch[8];
#pragma unroll
        for (int j = 0; j < 8; j++) {
            ch[j] = g * CG + cols[j];
            if (cols[j] < Nc) {
                float s = q1[ch[j]] * rsqrtf(q4[ch[j]] + BNEPS);
                sc[j] = s;
                bi[j] = (q0[ch[j]] - q3[ch[j]]) * s + q2[ch[j]];
            } else { sc[j] = 0.f; bi[j] = 0.f; }
        }
#pragma unroll
        for (int i = 0; i < 8; i++) {
            if (rows[i] >= M) continue;
            __nv_bfloat16* ya = d_ya + ((size_t)b * NN + rows[i]) * FKTOT;
#pragma unroll
            for (int j = 0; j < 8; j++)
                if (cols[j] < Nc) {
                    float t2 = acc[i][j] * sc[j] + bi[j];
                    float yv = t2 * normcdff(t2);            // exact GELU
                    __nv_bfloat16 hb16 = __float2bfloat16(yv);
                    __nv_bfloat16 lb16 = __float2bfloat16(yv - __bfloat162float(hb16));
                    ya[ch[j]]            = hb16;
                    ya[CC2 + ch[j]]      = hb16;
                    ya[2 * CC2 + ch[j]]  = lb16;
                }
        }
    }
}

// ---------------- L2 normalize + sq + bf16 hi/lo concat buffers --------------
__global__ void norm_kernel() {
    int row = blockIdx.x;
    const float* hr = d_h + (size_t)row * CC;
    int t = threadIdx.x;                    // 64 threads
    float a0 = hr[t], a1 = hr[t + 64], a2 = hr[t + 128];
    float ss = a0 * a0 + a1 * a1 + a2 * a2;
#pragma unroll
    for (int o = 16; o > 0; o >>= 1) ss += __shfl_down_sync(0xffffffffu, ss, o);
    __shared__ float w1[2], w2[2];
    if ((t & 31) == 0) w1[t >> 5] = ss;
    __syncthreads();
    float norm = sqrtf(w1[0] + w1[1]);
    float inv = 1.0f / fmaxf(norm, 1e-12f);
    float xv[3] = { a0 * inv, a1 * inv, a2 * inv };
    float s2 = xv[0] * xv[0] + xv[1] * xv[1] + xv[2] * xv[2];
#pragma unroll
    for (int o = 16; o > 0; o >>= 1) s2 += __shfl_down_sync(0xffffffffu, s2, o);
    if ((t & 31) == 0) w2[t >> 5] = s2;

    __nv_bfloat16* xa = d_xa + (size_t)row * KTOT;
    __nv_bfloat16* xb = d_xb + (size_t)row * KTOT;
#pragma unroll
    for (int e = 0; e < 3; e++) {
        int c = t + e * 64;
        float x = xv[e];
        __nv_bfloat16 h = __float2bfloat16(x);
        __nv_bfloat16 l = __float2bfloat16(x - __bfloat162float(h));
        xa[c]       = h;  xa[192 + c] = h;  xa[384 + c] = l;
        xb[c]       = h;  xb[192 + c] = l;  xb[384 + c] = h;
    }
    __syncthreads();
    if (t == 0) d_sq[row] = w2[0] + w2[1];
}

// ---------------- dist via mma.sync bf16 (K=576 concat split) ----------------
// CTA 128x128, 8 warps 4(m)x2(n), warp tile 32x64, K-slab 64, cp.async dbl-buf.
#define SROW 144                       // smem tile row bytes (72 bf16: 64 + 8 pad)
#define TILE_B (128 * SROW)            // 18432
#define SM_R   0                       // 12544 B
#define SM_IDX 12544                   // 2048 B (yyR,xxR,yyC,xxC int[128])
#define SM_BUF 14592
#define DS_STRIDE 133
#define DSM_TOTAL (SM_BUF + 4 * TILE_B)   // 88320 (>= SM_BUF + 128*133*4)
__global__ void __launch_bounds__(256)
dist_mma_kernel() {
    if (blockIdx.y > blockIdx.x) return;
    extern __shared__ char smem[];
    const int tid = threadIdx.x, w = tid >> 5, lane = tid & 31;
    const int b = blockIdx.z;
    const int m0 = blockIdx.y * 128, n0 = blockIdx.x * 128;

    float* Rs  = reinterpret_cast<float*>(smem + SM_R);
    int*   yyR = reinterpret_cast<int*>(smem + SM_IDX);
    int*   xxR = yyR + 128;
    int*   yyC = yyR + 256;
    int*   xxC = yyR + 384;

    for (int i = tid; i < 56 * 56; i += 256) Rs[i] = d_R[i];
    if (tid < 128) {
        int rg = min(m0 + tid, NN - 1);
        yyR[tid] = rg / 56; xxR[tid] = rg - (rg / 56) * 56;
        int cg = min(n0 + tid, NN - 1);
        yyC[tid] = cg / 56; xxC[tid] = cg - (cg / 56) * 56;
    }

    const uint32_t sbuf = smem_u32(smem + SM_BUF);
    const uint32_t sAq[2] = { sbuf, sbuf + TILE_B };
    const uint32_t sBq[2] = { sbuf + 2 * TILE_B, sbuf + 3 * TILE_B };

    const __nv_bfloat16* baseA = d_xa + (size_t)b * NN * KTOT;
    const __nv_bfloat16* baseB = d_xb + (size_t)b * NN * KTOT;

    auto issue = [&](int s) {
        const int k0b = s * KSLAB * 2;
        const uint32_t dA = sAq[s & 1], dB = sBq[s & 1];
#pragma unroll
        for (int c = 0; c < 4; c++) {
            int ch = tid + c * 256;
            int row = ch >> 3, cg = (ch & 7) * 16;
            const char* ga = (const char*)(baseA + (size_t)min(m0 + row, NN - 1) * KTOT) + k0b + cg;
            const char* gb = (const char*)(baseB + (size_t)min(n0 + row, NN - 1) * KTOT) + k0b + cg;
            uint32_t off = row * SROW + cg;
            asm volatile("cp.async.cg.shared.global [%0], [%1], 16;" :: "r"(dA + off), "l"(ga));
            asm volatile("cp.async.cg.shared.global [%0], [%1], 16;" :: "r"(dB + off), "l"(gb));
        }
        asm volatile("cp.async.commit_group;" ::: "memory");
    };

    issue(0);
    issue(1);

    float acc[2][8][4];
#pragma unroll
    for (int i = 0; i < 2; i++)
#pragma unroll
        for (int j = 0; j < 8; j++)
#pragma unroll
            for (int k = 0; k < 4; k++) acc[i][j][k] = 0.0f;

    const int wm = w & 3;
    const int wn = w >> 2;
    const int aRow  = lane & 15;
    const int aColB = ((lane >> 4) * 8) * 2;
    const int bNr   = ((lane >> 4) << 3) + (lane & 7);
    const int bColB = (((lane >> 3) & 1) * 8) * 2;

    for (int s = 0; s < NSLABS; s++) {
        if (s < NSLABS - 1)
            asm volatile("cp.async.wait_group 1;" ::: "memory");
        else
            asm volatile("cp.async.wait_group 0;" ::: "memory");
        __syncthreads();
        const uint32_t cA = sAq[s & 1], cB = sBq[s & 1];
#pragma unroll
        for (int kk = 0; kk < 4; kk++) {
            const int k0b = kk * 32;
            uint32_t af[2][4];
#pragma unroll
            for (int mi = 0; mi < 2; mi++) {
                uint32_t addr = cA + (wm * 32 + mi * 16 + aRow) * SROW + k0b + aColB;
                asm volatile(
                    "ldmatrix.sync.aligned.m8n8.x4.shared.b16 {%0,%1,%2,%3}, [%4];"
                    : "=r"(af[mi][0]), "=r"(af[mi][1]), "=r"(af[mi][2]), "=r"(af[mi][3])
                    : "r"(addr));
            }
            uint32_t bfv[4][4];
#pragma unroll
            for (int nb = 0; nb < 4; nb++) {
                uint32_t addr = cB + (wn * 64 + nb * 16 + bNr) * SROW + k0b + bColB;
                asm volatile(
                    "ldmatrix.sync.aligned.m8n8.x4.shared.b16 {%0,%1,%2,%3}, [%4];"
                    : "=r"(bfv[nb][0]), "=r"(bfv[nb][1]), "=r"(bfv[nb][2]), "=r"(bfv[nb][3])
                    : "r"(addr));
            }
#pragma unroll
            for (int mi = 0; mi < 2; mi++)
#pragma unroll
                for (int ni = 0; ni < 8; ni++) {
                    uint32_t b0 = bfv[ni >> 1][(ni & 1) * 2 + 0];
                    uint32_t b1 = bfv[ni >> 1][(ni & 1) * 2 + 1];
                    asm volatile(
                        "mma.sync.aligned.m16n8k16.row.col.f32.bf16.bf16.f32 "
                        "{%0,%1,%2,%3}, {%4,%5,%6,%7}, {%8,%9}, {%0,%1,%2,%3};"
                        : "+f"(acc[mi][ni][0]), "+f"(acc[mi][ni][1]),
                          "+f"(acc[mi][ni][2]), "+f"(acc[mi][ni][3])
                        : "r"(af[mi][0]), "r"(af[mi][1]), "r"(af[mi][2]), "r"(af[mi][3]),
                          "r"(b0), "r"(b1));
                }
        }
        __syncthreads();
        if (s + 2 < NSLABS) issue(s + 2);
    }

    // ---- stage C to smem [128][133]
    float* Ds = reinterpret_cast<float*>(smem + SM_BUF);
#pragma unroll
    for (int mi = 0; mi < 2; mi++) {
        int r0 = wm * 32 + mi * 16 + (lane >> 2);
        int c0 = wn * 64 + (lane & 3) * 2;
#pragma unroll
        for (int ni = 0; ni < 8; ni++) {
            int cc = c0 + ni * 8;
            Ds[r0 * DS_STRIDE + cc]           = acc[mi][ni][0];
            Ds[r0 * DS_STRIDE + cc + 1]       = acc[mi][ni][1];
            Ds[(r0 + 8) * DS_STRIDE + cc]     = acc[mi][ni][2];
            Ds[(r0 + 8) * DS_STRIDE + cc + 1] = acc[mi][ni][3];
        }
    }
    __syncthreads();

    float* db = d_dist + (size_t)b * NN * NN;
    const float* sqb = d_sq + b * NN;

    // phase 1: mirror tile
    if (blockIdx.x != blockIdx.y) {
        for (int cl = w; cl < 128; cl += 8) {
            int m = n0 + cl;
            if (m >= NN) continue;
            float* dbm = db + (size_t)m * NN;
            const int yc = yyC[cl], xc = xxC[cl];
#pragma unroll
            for (int rq = 0; rq < 4; rq++) {
                int rl = rq * 32 + lane;
                int rg = m0 + rl;
                if (rg >= NN) continue;
                float v = Ds[rl * DS_STRIDE + cl];
                float relv = Rs[yyR[rl] * 56 + yc] + Rs[xxR[rl] * 56 + xc];
                dbm[rg] = sqb[rg] - 2.0f * v + relv;
            }
        }
    }

    // phase 2: normal tile
    {
        const int c = tid & 127;
        const int rh = (tid >> 7) * 64;
        const int gc = n0 + c;
        if (gc < NN) {
            const float sqc = sqb[gc];
            const int yc = yyC[c], xc = xxC[c];
#pragma unroll 1
            for (int r = 0; r < 64; r++) {
                int rl = rh + r;
                int rg = m0 + rl;
                if (rg >= NN) break;
                float v = Ds[rl * DS_STRIDE + c];
                float relv = Rs[yyR[rl] * 56 + yc] + Rs[xxR[rl] * 56 + xc];
                db[(size_t)rg * NN + gc] = sqc - 2.0f * v + relv;
            }
        }
    }
}

// ---------------- fc2 via mma.sync bf16 (K=1152 concat split) ----------------
// CTA 128x128, 8 warps 4x2; epilogue BN2 + transposed residual write -> out
#define F_TOTAL (4 * TILE_B)           // 73728 (> 128*133*4 = 68096 staging)
__global__ void __launch_bounds__(256)
fc2_mma_kernel(const float* __restrict__ q0, const float* __restrict__ q1,
               const float* __restrict__ q2, const float* __restrict__ q3,
               const float* __restrict__ q4,
               const float* __restrict__ xres, float* __restrict__ outp)
{
    extern __shared__ char smem[];
    const int tid = threadIdx.x, w = tid >> 5, lane = tid & 31;
    const int m0 = blockIdx.y * 128, n0 = blockIdx.x * 128;

    const uint32_t sbuf = smem_u32(smem);
    const uint32_t sAq[2] = { sbuf, sbuf + TILE_B };
    const uint32_t sBq[2] = { sbuf + 2 * TILE_B, sbuf + 3 * TILE_B };

    auto issue = [&](int s) {
        const int k0b = s * KSLAB * 2;
        const uint32_t dA = sAq[s & 1], dB = sBq[s & 1];
#pragma unroll
        for (int c = 0; c < 4; c++) {
            int ch = tid + c * 256;
            int row = ch >> 3, cg = (ch & 7) * 16;
            const char* ga = (const char*)(d_ya + (size_t)(m0 + row) * FKTOT) + k0b + cg;
            const char* gb = (const char*)(d_wb + (size_t)min(n0 + row, CC - 1) * FKTOT) + k0b + cg;
            uint32_t off = row * SROW + cg;
            asm volatile("cp.async.cg.shared.global [%0], [%1], 16;" :: "r"(dA + off), "l"(ga));
            asm volatile("cp.async.cg.shared.global [%0], [%1], 16;" :: "r"(dB + off), "l"(gb));
        }
        asm volatile("cp.async.commit_group;" ::: "memory");
    };

    issue(0);
    issue(1);

    float acc[2][8][4];
#pragma unroll
    for (int i = 0; i < 2; i++)
#pragma unroll
        for (int j = 0; j < 8; j++)
#pragma unroll
            for (int k = 0; k < 4; k++) acc[i][j][k] = 0.0f;

    const int wm = w & 3;
    const int wn = w >> 2;
    const int aRow  = lane & 15;
    const int aColB = ((lane >> 4) * 8) * 2;
    const int bNr   = ((lane >> 4) << 3) + (lane & 7);
    const int bColB = (((lane >> 3) & 1) * 8) * 2;

    for (int s = 0; s < FNSLABS; s++) {
        if (s < FNSLABS - 1)
            asm volatile("cp.async.wait_group 1;" ::: "memory");
        else
            asm volatile("cp.async.wait_group 0;" ::: "memory");
        __syncthreads();
        const uint32_t cA = sAq[s & 1], cB = sBq[s & 1];
#pragma unroll
        for (int kk = 0; kk < 4; kk++) {
            const int k0b = kk * 32;
            uint32_t af[2][4];
#pragma unroll
            for (int mi = 0; mi < 2; mi++) {
                uint32_t addr = cA + (wm * 32 + mi * 16 + aRow) * SROW + k0b + aColB;
                asm volatile(
                    "ldmatrix.sync.aligned.m8n8.x4.shared.b16 {%0,%1,%2,%3}, [%4];"
                    : "=r"(af[mi][0]), "=r"(af[mi][1]), "=r"(af[mi][2]), "=r"(af[mi][3])
                    : "r"(addr));
            }
            uint32_t bfv[4][4];
#pragma unroll
            for (int nb = 0; nb < 4; nb++) {
                uint32_t addr = cB + (wn * 64 + nb * 16 + bNr) * SROW + k0b + bColB;
                asm volatile(
                    "ldmatrix.sync.aligned.m8n8.x4.shared.b16 {%0,%1,%2,%3}, [%4];"
                    : "=r"(bfv[nb][0]), "=r"(bfv[nb][1]), "=r"(bfv[nb][2]), "=r"(bfv[nb][3])
                    : "r"(addr));
            }
#pragma unroll
            for (int mi = 0; mi < 2; mi++)
#pragma unroll
                for (int ni = 0; ni < 8; ni++) {
                    uint32_t b0 = bfv[ni >> 1][(ni & 1) * 2 + 0];
                    uint32_t b1 = bfv[ni >> 1][(ni & 1) * 2 + 1];
                    asm volatile(
                        "mma.sync.aligned.m16n8k16.row.col.f32.bf16.bf16.f32 "
                        "{%0,%1,%2,%3}, {%4,%5,%6,%7}, {%8,%9}, {%0,%1,%2,%3};"
                        : "+f"(acc[mi][ni][0]), "+f"(acc[mi][ni][1]),
                          "+f"(acc[mi][ni][2]), "+f"(acc[mi][ni][3])
                        : "r"(af[mi][0]), "r"(af[mi][1]), "r"(af[mi][2]), "r"(af[mi][3]),
                          "r"(b0), "r"(b1));
                }
        }
        __syncthreads();
        if (s + 2 < FNSLABS) issue(s + 2);
    }

    // ---- stage C to smem [128][133]
    float* Ds = reinterpret_cast<float*>(smem);
#pragma unroll
    for (int mi = 0; mi < 2; mi++) {
        int r0 = wm * 32 + mi * 16 + (lane >> 2);
        int c0 = wn * 64 + (lane & 3) * 2;
#pragma unroll
        for (int ni = 0; ni < 8; ni++) {
            int cc = c0 + ni * 8;
            Ds[r0 * DS_STRIDE + cc]           = acc[mi][ni][0];
            Ds[r0 * DS_STRIDE + cc + 1]       = acc[mi][ni][1];
            Ds[(r0 + 8) * DS_STRIDE + cc]     = acc[mi][ni][2];
            Ds[(r0 + 8) * DS_STRIDE + cc + 1] = acc[mi][ni][3];
        }
    }
    __syncthreads();

    // BN2 + transposed residual write: warp = column, lanes = consecutive rows
    for (int cl = w; cl < 128; cl += 8) {
        int gc = n0 + cl;
        if (gc >= CC) continue;
        float s = q1[gc] * rsqrtf(q4[gc] + BNEPS);
        float bi = (q0[gc] - q3[gc]) * s + q2[gc];
#pragma unroll
        for (int rq = 0; rq < 4; rq++) {
            int rl = rq * 32 + lane;
            int rg = m0 + rl;                // < 25088 always (196*128)
            int bb = rg / NN, nn2 = rg - bb * NN;
            size_t o = ((size_t)bb * CC + gc) * NN + nn2;
            float v = Ds[rl * DS_STRIDE + cl];
            outp[o] = v * s + bi + xres[o];
        }
    }
}

// ---------------- fused top-9 + gather/max-edge (4 rows per block) -----------
__global__ void __launch_bounds__(256) topk_gather_kernel() {
    const int r = threadIdx.x >> 6;
    const int g = threadIdx.x & 63;
    const int row = blockIdx.x * 4 + r;
    const int b = row / NN, n = row % NN;
    const float4* dr4 = reinterpret_cast<const float4*>(
        d_dist + (size_t)b * NN * NN + (size_t)n * NN);

    float tv[KNB];
    int   ti[KNB];
#pragma unroll
    for (int q = 0; q < KNB; q++) { tv[q] = INFINITY; ti[q] = 0x7fffffff; }

    for (int i4 = g; i4 < NN / 4; i4 += 64) {
        float4 v4 = dr4[i4];
        const int mb = i4 * 4;
        float vv[4] = { v4.x, v4.y, v4.z, v4.w };
#pragma unroll
        for (int c = 0; c < 4; c++) {
            float v = vv[c];
            if (v < tv[KNB - 1]) {
                tv[KNB - 1] = v; ti[KNB - 1] = mb + c;
#pragma unroll
                for (int q = KNB - 1; q > 0; q--) {
                    if (tv[q] < tv[q - 1]) {
                        float fv = tv[q]; tv[q] = tv[q - 1]; tv[q - 1] = fv;
                        int   fi = ti[q]; ti[q] = ti[q - 1]; ti[q - 1] = fi;
                    }
                }
            }
        }
    }

    __shared__ float sv[256 * KNB];
    __shared__ int   si[256 * KNB];
#pragma unroll
    for (int q = 0; q < KNB; q++) {
        sv[threadIdx.x * KNB + q] = tv[q];
        si[threadIdx.x * KNB + q] = ti[q];
    }

    for (int stride = 32; stride >= 1; stride >>= 1) {
        __syncthreads();
        if (g < (unsigned)stride) {
            float* Av = &sv[(r * 64 + g) * KNB];
            int*   Ai = &si[(r * 64 + g) * KNB];
            float* Bv = &sv[(r * 64 + g + stride) * KNB];
            int*   Bi = &si[(r * 64 + g + stride) * KNB];
            float ov[KNB]; int oi[KNB];
            int ia = 0, ib = 0;
#pragma unroll
            for (int q = 0; q < KNB; q++) {
                float va = (ia < KNB) ? Av[ia] : INFINITY;
                float vb = (ib < KNB) ? Bv[ib] : INFINITY;
                int xa = (ia < KNB) ? Ai[ia] : 0x7fffffff;
                int xb = (ib < KNB) ? Bi[ib] : 0x7fffffff;
                bool takeA = (va < vb) || (va == vb && xa < xb);
                ov[q] = takeA ? va : vb;
                oi[q] = takeA ? xa : xb;
                if (takeA) ia++; else ib++;
            }
#pragma unroll
            for (int q = 0; q < KNB; q++) { Av[q] = ov[q]; Ai[q] = oi[q]; }
        }
    }
    __syncthreads();

    {
        const int* nn9 = &si[(r * 64) * KNB];
        const float* hb = d_h + (size_t)b * NN * CC;
        const float* hr = d_h + (size_t)row * CC;
        float* gb = d_gbuf + (size_t)row * CC2;
#pragma unroll
        for (int e = 0; e < 3; e++) {
            int c = g + e * 64;
            float hn = hr[c];
            float mx = -INFINITY;
#pragma unroll
            for (int j = 0; j < KNB; j++)
                mx = fmaxf(mx, hb[(size_t)nn9[j] * CC + c] - hn);
            gb[c]      = hn;
            gb[CC + c] = mx;
        }
    }
}

// ---------------- launch ----------------------------------------------------
extern "C" void kernel_launch(void* const* d_in, const int* in_sizes, int n_in,
                              void* d_out, int out_size)
{
    (void)in_sizes; (void)n_in; (void)out_size;
    const float* x     = (const float*)d_in[0];
    const float* fc1_w = (const float*)d_in[1];
    const float* fc1_b = (const float*)d_in[2];
    const float* bn1_g = (const float*)d_in[3];
    const float* bn1_b = (const float*)d_in[4];
    const float* bn1_m = (const float*)d_in[5];
    const float* bn1_v = (const float*)d_in[6];
    const float* gc_w  = (const float*)d_in[7];
    const float* gc_b  = (const float*)d_in[8];
    const float* bng_g = (const float*)d_in[9];
    const float* bng_b = (const float*)d_in[10];
    const float* bng_m = (const float*)d_in[11];
    const float* bng_v = (const float*)d_in[12];
    const float* fc2_w = (const float*)d_in[13];
    const float* fc2_b = (const float*)d_in[14];
    const float* bn2_g = (const float*)d_in[15];
    const float* bn2_b = (const float*)d_in[16];
    const float* bn2_m = (const float*)d_in[17];
    const float* bn2_v = (const float*)d_in[18];
    float* out = (float*)d_out;

    cudaFuncSetAttribute(dist_mma_kernel,
                         cudaFuncAttributeMaxDynamicSharedMemorySize, DSM_TOTAL);
    cudaFuncSetAttribute(fc2_mma_kernel,
                         cudaFuncAttributeMaxDynamicSharedMemorySize, F_TOTAL);

    // 1: rel position table (56x56)
    rel_table_kernel<<<25, 128>>>();
    // 2: fc1 + bn1 -> h
    gemm_kernel<0><<<dim3(2, 25, BB), 256>>>(x, fc1_w, fc1_b, bn1_g, bn1_b, bn1_m, bn1_v);
    // 3: normalize rows -> sq + bf16 concat split buffers
    norm_kernel<<<BB * NN, 64>>>();
    // 4: dist via mma.sync bf16 split  [ncu capture slot]
    dist_mma_kernel<<<dim3(25, 25, BB), 256, DSM_TOTAL>>>();
    // 5: split fc2_w -> d_wb
    wsplit_kernel<<<(CC * CC2 + 255) / 256, 256>>>(fc2_w);
    // 6: fused top-9 + gather/max-edge, 4 rows/block -> g = [h, d]
    topk_gather_kernel<<<BB * NN / 4, 256>>>();
    // 7: grouped conv + bn + gelu -> d_ya (bf16 split concat)
    gemm_kernel<3><<<dim3(1, 25, BB * 4), 256>>>(nullptr, gc_w, gc_b, bng_g, bng_b, bng_m, bng_v);
    // 8: fc2 via mma + bn2 + transpose + residual -> out
    fc2_mma_kernel<<<dim3(2, 196, 1), 256, F_TOTAL>>>(fc2_b, bn2_g, bn2_b, bn2_m, bn2_v, x, out);
}

// round 17
// speedup vs baseline: 1.0956x; 1.0020x over previous
#include <cuda_runtime.h>
#include <cuda_bf16.h>
#include <math.h>
#include <stdint.h>

// Problem constants (fixed shapes from setup_inputs)
#define BB  8
#define CC  192
#define HH  56
#define WW  56
#define NN  3136            // H*W
#define CC2 384             // 2*C
#define CG  96              // C2/4
#define KNB 9               // K_NEIGHBORS
#define BNEPS 1e-5f
#define KSLAB 64
#define NSLABS 9            // dist: 3*192/64
#define MTOT (BB * NN)      // 25088

// ---------------- scratch (static device globals; no runtime alloc) --------
__device__ float d_R   [56 * 56];                          // rel position table
__device__ float d_h   [(size_t)MTOT * CC];                // 19.3 MB
__device__ __nv_bfloat16 d_xt[(size_t)MTOT * 384];         // 19.3 MB x^T split [h|l]
__device__ __nv_bfloat16 d_xc[(size_t)MTOT * 384];         // 19.3 MB xn split [h|l]
__device__ float d_sq  [MTOT];
__device__ float d_dist[(size_t)BB * NN * NN];             // 314.7 MB
__device__ float d_gbuf[(size_t)MTOT * CC2];               // 38.6 MB
__device__ __nv_bfloat16 d_ya[(size_t)MTOT * 768];         // 38.6 MB y split [h|l]
__device__ __nv_bfloat16 d_w1[CC * 384];                   // fc1_w split [h|l]
__device__ __nv_bfloat16 d_wb[CC * 768];                   // fc2_w split [h|l]

__device__ __forceinline__ uint32_t smem_u32(const void* p) {
    uint32_t a;
    asm("{ .reg .u64 t; cvta.to.shared.u64 t, %1; cvt.u32.u64 %0, t; }"
        : "=r"(a) : "l"(p));
    return a;
}

// ---------------- rel position table -----------------------------------------
__global__ void rel_table_kernel() {
    int p = blockIdx.x * 128 + threadIdx.x;
    if (p >= 56 * 56) return;
    int a = p / 56, b = p - (p / 56) * 56;
    float s = 0.0f;
#pragma unroll 1
    for (int i = 0; i < 48; i++) {
        float wv = expf(-logf(10000.0f) * (float)i / 48.0f);
        float sa, ca, sb, cb;
        sincosf((float)a * wv, &sa, &ca);
        sincosf((float)b * wv, &sb, &cb);
        s += sa * sb + ca * cb;
    }
    d_R[p] = (-2.0f / (float)CC) * s;
}

// ---------------- weight splits ----------------------------------------------
__global__ void w1split_kernel(const float* __restrict__ w) {
    int i = blockIdx.x * 256 + threadIdx.x;       // 192*192
    if (i >= CC * CC) return;
    int d = i / CC, k = i - (i / CC) * CC;
    float v = w[i];
    __nv_bfloat16 h = __float2bfloat16(v);
    __nv_bfloat16 l = __float2bfloat16(v - __bfloat162float(h));
    d_w1[(size_t)d * 384 + k]       = h;
    d_w1[(size_t)d * 384 + 192 + k] = l;
}
__global__ void wsplit_kernel(const float* __restrict__ w) {
    int i = blockIdx.x * 256 + threadIdx.x;       // 192*384
    if (i >= CC * CC2) return;
    int d = i / CC2, k = i - (i / CC2) * CC2;
    float v = w[i];
    __nv_bfloat16 h = __float2bfloat16(v);
    __nv_bfloat16 l = __float2bfloat16(v - __bfloat162float(h));
    d_wb[(size_t)d * 768 + k]       = h;
    d_wb[(size_t)d * 768 + CC2 + k] = l;
}

// ---------------- transpose-split x (B,C,N) -> d_xt[(b,n)][h|l] --------------
__global__ void xt_split_kernel(const float* __restrict__ x) {
    __shared__ float tile[32][33];
    const int b = blockIdx.z;
    const int n0 = blockIdx.x * 32, c0 = blockIdx.y * 32;
    const int tx = threadIdx.x, ty = threadIdx.y;
#pragma unroll
    for (int i = 0; i < 32; i += 8)
        tile[ty + i][tx] = x[((size_t)b * CC + c0 + ty + i) * NN + n0 + tx];
    __syncthreads();
#pragma unroll
    for (int i = 0; i < 32; i += 8) {
        int n = n0 + ty + i, c = c0 + tx;
        float v = tile[tx][ty + i];
        __nv_bfloat16 h = __float2bfloat16(v);
        __nv_bfloat16 l = __float2bfloat16(v - __bfloat162float(h));
        __nv_bfloat16* row = d_xt + ((size_t)b * NN + n) * 384;
        row[c] = h; row[192 + c] = l;
    }
}

// ---------------- grouped conv SGEMM (SIMT) -----------------------------------
// A = d_gbuf slice, B = gc_w[g]; bias+BN+GELU -> d_ya split [h|l]
__global__ void __launch_bounds__(256, 2)
group_gemm_kernel(const float* __restrict__ Bin,
                  const float* __restrict__ q0, const float* __restrict__ q1,
                  const float* __restrict__ q2, const float* __restrict__ q3,
                  const float* __restrict__ q4)
{
    const int bz = blockIdx.z;
    const int b = bz >> 2, g = bz & 3;
    const float* A = d_gbuf + (size_t)b * NN * CC2 + g * CG;
    const float* B = Bin + (size_t)g * CG * CG;
    const int M = NN, Nc = CG, K = CG, lda = CC2, ldb = CG;

    __shared__ float As[2][16][128];
    __shared__ float Bs[2][16][128];

    const int tid = threadIdx.x;
    const int tx = tid & 15;
    const int ty = tid >> 4;
    const int m0 = blockIdx.y * 128;
    const int n0 = blockIdx.x * 128;

    const int a_rm_r  = tid >> 1;
    const int a_rm_kq = (tid & 1) * 8;
    const float* aptr0 = A + (size_t)min(m0 + a_rm_r, M - 1) * lda + a_rm_kq;
    const float* aptr1 = aptr0 + 4;
    const int b_rm_r  = tid >> 1;
    const int b_rm_kq = (tid & 1) * 8;
    const float* bptr0 = B + (size_t)min(n0 + b_rm_r, Nc - 1) * ldb + b_rm_kq;
    const float* bptr1 = bptr0 + 4;

    float4 ra0, ra1, rb0, rb1;
    ra0 = *reinterpret_cast<const float4*>(aptr0);
    ra1 = *reinterpret_cast<const float4*>(aptr1);
    rb0 = *reinterpret_cast<const float4*>(bptr0);
    rb1 = *reinterpret_cast<const float4*>(bptr1);
    As[0][a_rm_kq + 0][a_rm_r] = ra0.x; As[0][a_rm_kq + 1][a_rm_r] = ra0.y;
    As[0][a_rm_kq + 2][a_rm_r] = ra0.z; As[0][a_rm_kq + 3][a_rm_r] = ra0.w;
    As[0][a_rm_kq + 4][a_rm_r] = ra1.x; As[0][a_rm_kq + 5][a_rm_r] = ra1.y;
    As[0][a_rm_kq + 6][a_rm_r] = ra1.z; As[0][a_rm_kq + 7][a_rm_r] = ra1.w;
    Bs[0][b_rm_kq + 0][b_rm_r] = rb0.x; Bs[0][b_rm_kq + 1][b_rm_r] = rb0.y;
    Bs[0][b_rm_kq + 2][b_rm_r] = rb0.z; Bs[0][b_rm_kq + 3][b_rm_r] = rb0.w;
    Bs[0][b_rm_kq + 4][b_rm_r] = rb1.x; Bs[0][b_rm_kq + 5][b_rm_r] = rb1.y;
    Bs[0][b_rm_kq + 6][b_rm_r] = rb1.z; Bs[0][b_rm_kq + 7][b_rm_r] = rb1.w;
    __syncthreads();

    float acc[8][8];
#pragma unroll
    for (int i = 0; i < 8; i++)
#pragma unroll
        for (int j = 0; j < 8; j++) acc[i][j] = 0.0f;

    const int T = K >> 4;
    for (int t = 0; t < T; t++) {
        const int cur = t & 1;
        if (t + 1 < T) {
            aptr0 += 16; aptr1 += 16; bptr0 += 16; bptr1 += 16;
            ra0 = *reinterpret_cast<const float4*>(aptr0);
            ra1 = *reinterpret_cast<const float4*>(aptr1);
            rb0 = *reinterpret_cast<const float4*>(bptr0);
            rb1 = *reinterpret_cast<const float4*>(bptr1);
        }
#pragma unroll
        for (int kk = 0; kk < 16; kk++) {
            float af[8], bf[8];
            *reinterpret_cast<float4*>(&af[0]) = *reinterpret_cast<const float4*>(&As[cur][kk][ty * 4]);
            *reinterpret_cast<float4*>(&af[4]) = *reinterpret_cast<const float4*>(&As[cur][kk][64 + ty * 4]);
            *reinterpret_cast<float4*>(&bf[0]) = *reinterpret_cast<const float4*>(&Bs[cur][kk][tx * 4]);
            *reinterpret_cast<float4*>(&bf[4]) = *reinterpret_cast<const float4*>(&Bs[cur][kk][64 + tx * 4]);
#pragma unroll
            for (int i = 0; i < 8; i++)
#pragma unroll
                for (int j = 0; j < 8; j++) acc[i][j] += af[i] * bf[j];
        }
        if (t + 1 < T) {
            const int nxt = cur ^ 1;
            As[nxt][a_rm_kq + 0][a_rm_r] = ra0.x; As[nxt][a_rm_kq + 1][a_rm_r] = ra0.y;
            As[nxt][a_rm_kq + 2][a_rm_r] = ra0.z; As[nxt][a_rm_kq + 3][a_rm_r] = ra0.w;
            As[nxt][a_rm_kq + 4][a_rm_r] = ra1.x; As[nxt][a_rm_kq + 5][a_rm_r] = ra1.y;
            As[nxt][a_rm_kq + 6][a_rm_r] = ra1.z; As[nxt][a_rm_kq + 7][a_rm_r] = ra1.w;
            Bs[nxt][b_rm_kq + 0][b_rm_r] = rb0.x; Bs[nxt][b_rm_kq + 1][b_rm_r] = rb0.y;
            Bs[nxt][b_rm_kq + 2][b_rm_r] = rb0.z; Bs[nxt][b_rm_kq + 3][b_rm_r] = rb0.w;
            Bs[nxt][b_rm_kq + 4][b_rm_r] = rb1.x; Bs[nxt][b_rm_kq + 5][b_rm_r] = rb1.y;
            Bs[nxt][b_rm_kq + 6][b_rm_r] = rb1.z; Bs[nxt][b_rm_kq + 7][b_rm_r] = rb1.w;
        }
        __syncthreads();
    }

    int rows[8], cols[8];
#pragma unroll
    for (int i = 0; i < 4; i++) {
        rows[i]     = m0 + ty * 4 + i;
        rows[i + 4] = m0 + 64 + ty * 4 + i;
        cols[i]     = n0 + tx * 4 + i;
        cols[i + 4] = n0 + 64 + tx * 4 + i;
    }

    float sc[8], bi[8];
    int ch[8];
#pragma unroll
    for (int j = 0; j < 8; j++) {
        ch[j] = g * CG + cols[j];
        if (cols[j] < Nc) {
            float s = q1[ch[j]] * rsqrtf(q4[ch[j]] + BNEPS);
            sc[j] = s;
            bi[j] = (q0[ch[j]] - q3[ch[j]]) * s + q2[ch[j]];
        } else { sc[j] = 0.f; bi[j] = 0.f; }
    }
#pragma unroll
    for (int i = 0; i < 8; i++) {
        if (rows[i] >= M) continue;
        __nv_bfloat16* ya = d_ya + ((size_t)b * NN + rows[i]) * 768;
#pragma unroll
        for (int j = 0; j < 8; j++)
            if (cols[j] < Nc) {
                float t2 = acc[i][j] * sc[j] + bi[j];
                float yv = t2 * normcdff(t2);            // exact GELU
                __nv_bfloat16 hb16 = __float2bfloat16(yv);
                __nv_bfloat16 lb16 = __float2bfloat16(yv - __bfloat162float(hb16));
                ya[ch[j]]       = hb16;
                ya[CC2 + ch[j]] = lb16;
            }
    }
}

// ---------------- L2 normalize + sq -> d_xc split [h|l] -----------------------
__global__ void norm_kernel() {
    int row = blockIdx.x;
    const float* hr = d_h + (size_t)row * CC;
    int t = threadIdx.x;                    // 64 threads
    float a0 = hr[t], a1 = hr[t + 64], a2 = hr[t + 128];
    float ss = a0 * a0 + a1 * a1 + a2 * a2;
#pragma unroll
    for (int o = 16; o > 0; o >>= 1) ss += __shfl_down_sync(0xffffffffu, ss, o);
    __shared__ float w1[2], w2[2];
    if ((t & 31) == 0) w1[t >> 5] = ss;
    __syncthreads();
    float norm = sqrtf(w1[0] + w1[1]);
    float inv = 1.0f / fmaxf(norm, 1e-12f);
    float xv[3] = { a0 * inv, a1 * inv, a2 * inv };
    float s2 = xv[0] * xv[0] + xv[1] * xv[1] + xv[2] * xv[2];
#pragma unroll
    for (int o = 16; o > 0; o >>= 1) s2 += __shfl_down_sync(0xffffffffu, s2, o);
    if ((t & 31) == 0) w2[t >> 5] = s2;

    __nv_bfloat16* xc = d_xc + (size_t)row * 384;
#pragma unroll
    for (int e = 0; e < 3; e++) {
        int c = t + e * 64;
        float x = xv[e];
        __nv_bfloat16 h = __float2bfloat16(x);
        __nv_bfloat16 l = __float2bfloat16(x - __bfloat162float(h));
        xc[c] = h; xc[192 + c] = l;
    }
    __syncthreads();
    if (t == 0) d_sq[row] = w2[0] + w2[1];
}

// ---------------- dist via mma.sync bf16 (compact [h|l] + slab offsets) -------
#define SROW 144                       // smem tile row bytes (72 bf16)
#define TILE_B (128 * SROW)            // 18432
#define SM_R   0                       // 12544 B
#define SM_IDX 12544                   // 2048 B
#define SM_BUF 14592
#define DS_STRIDE 133
#define DSM_TOTAL (SM_BUF + 4 * TILE_B)   // 88320
__global__ void __launch_bounds__(256)
dist_mma_kernel() {
    if (blockIdx.y > blockIdx.x) return;
    extern __shared__ char smem[];
    const int tid = threadIdx.x, w = tid >> 5, lane = tid & 31;
    const int b = blockIdx.z;
    const int m0 = blockIdx.y * 128, n0 = blockIdx.x * 128;

    float* Rs  = reinterpret_cast<float*>(smem + SM_R);
    int*   yyR = reinterpret_cast<int*>(smem + SM_IDX);
    int*   xxR = yyR + 128;
    int*   yyC = yyR + 256;
    int*   xxC = yyR + 384;

    for (int i = tid; i < 56 * 56; i += 256) Rs[i] = d_R[i];
    if (tid < 128) {
        int rg = min(m0 + tid, NN - 1);
        yyR[tid] = rg / 56; xxR[tid] = rg - (rg / 56) * 56;
        int cg = min(n0 + tid, NN - 1);
        yyC[tid] = cg / 56; xxC[tid] = cg - (cg / 56) * 56;
    }

    const uint32_t sbuf = smem_u32(smem + SM_BUF);
    const uint32_t sAq[2] = { sbuf, sbuf + TILE_B };
    const uint32_t sBq[2] = { sbuf + 2 * TILE_B, sbuf + 3 * TILE_B };

    const __nv_bfloat16* base = d_xc + (size_t)b * NN * 384;

    auto issue = [&](int s) {
        // A pattern [h|h|l], B pattern [h|l|h] over compact [h|l] (192+192)
        const int offA = (s < 6) ? 64 * (s % 3) : 192 + 64 * (s - 6);
        const int offB = (s < 3) ? 64 * s : (s < 6) ? 192 + 64 * (s - 3) : 64 * (s - 6);
        const uint32_t dA = sAq[s & 1], dB = sBq[s & 1];
#pragma unroll
        for (int c = 0; c < 4; c++) {
            int ch = tid + c * 256;
            int row = ch >> 3, cg = (ch & 7) * 16;
            const char* ga = (const char*)(base + (size_t)min(m0 + row, NN - 1) * 384 + offA) + cg;
            const char* gb = (const char*)(base + (size_t)min(n0 + row, NN - 1) * 384 + offB) + cg;
            uint32_t off = row * SROW + cg;
            asm volatile("cp.async.cg.shared.global [%0], [%1], 16;" :: "r"(dA + off), "l"(ga));
            asm volatile("cp.async.cg.shared.global [%0], [%1], 16;" :: "r"(dB + off), "l"(gb));
        }
        asm volatile("cp.async.commit_group;" ::: "memory");
    };

    issue(0);
    issue(1);

    float acc[2][8][4];
#pragma unroll
    for (int i = 0; i < 2; i++)
#pragma unroll
        for (int j = 0; j < 8; j++)
#pragma unroll
            for (int k = 0; k < 4; k++) acc[i][j][k] = 0.0f;

    const int wm = w & 3;
    const int wn = w >> 2;
    const int aRow  = lane & 15;
    const int aColB = ((lane >> 4) * 8) * 2;
    const int bNr   = ((lane >> 4) << 3) + (lane & 7);
    const int bColB = (((lane >> 3) & 1) * 8) * 2;

    for (int s = 0; s < NSLABS; s++) {
        if (s < NSLABS - 1)
            asm volatile("cp.async.wait_group 1;" ::: "memory");
        else
            asm volatile("cp.async.wait_group 0;" ::: "memory");
        __syncthreads();
        const uint32_t cA = sAq[s & 1], cB = sBq[s & 1];
#pragma unroll
        for (int kk = 0; kk < 4; kk++) {
            const int k0b = kk * 32;
            uint32_t af[2][4];
#pragma unroll
            for (int mi = 0; mi < 2; mi++) {
                uint32_t addr = cA + (wm * 32 + mi * 16 + aRow) * SROW + k0b + aColB;
                asm volatile(
                    "ldmatrix.sync.aligned.m8n8.x4.shared.b16 {%0,%1,%2,%3}, [%4];"
                    : "=r"(af[mi][0]), "=r"(af[mi][1]), "=r"(af[mi][2]), "=r"(af[mi][3])
                    : "r"(addr));
            }
            uint32_t bfv[4][4];
#pragma unroll
            for (int nb = 0; nb < 4; nb++) {
                uint32_t addr = cB + (wn * 64 + nb * 16 + bNr) * SROW + k0b + bColB;
                asm volatile(
                    "ldmatrix.sync.aligned.m8n8.x4.shared.b16 {%0,%1,%2,%3}, [%4];"
                    : "=r"(bfv[nb][0]), "=r"(bfv[nb][1]), "=r"(bfv[nb][2]), "=r"(bfv[nb][3])
                    : "r"(addr));
            }
#pragma unroll
            for (int mi = 0; mi < 2; mi++)
#pragma unroll
                for (int ni = 0; ni < 8; ni++) {
                    uint32_t b0 = bfv[ni >> 1][(ni & 1) * 2 + 0];
                    uint32_t b1 = bfv[ni >> 1][(ni & 1) * 2 + 1];
                    asm volatile(
                        "mma.sync.aligned.m16n8k16.row.col.f32.bf16.bf16.f32 "
                        "{%0,%1,%2,%3}, {%4,%5,%6,%7}, {%8,%9}, {%0,%1,%2,%3};"
                        : "+f"(acc[mi][ni][0]), "+f"(acc[mi][ni][1]),
                          "+f"(acc[mi][ni][2]), "+f"(acc[mi][ni][3])
                        : "r"(af[mi][0]), "r"(af[mi][1]), "r"(af[mi][2]), "r"(af[mi][3]),
                          "r"(b0), "r"(b1));
                }
        }
        __syncthreads();
        if (s + 2 < NSLABS) issue(s + 2);
    }

    float* Ds = reinterpret_cast<float*>(smem + SM_BUF);
#pragma unroll
    for (int mi = 0; mi < 2; mi++) {
        int r0 = wm * 32 + mi * 16 + (lane >> 2);
        int c0 = wn * 64 + (lane & 3) * 2;
#pragma unroll
        for (int ni = 0; ni < 8; ni++) {
            int cc = c0 + ni * 8;
            Ds[r0 * DS_STRIDE + cc]           = acc[mi][ni][0];
            Ds[r0 * DS_STRIDE + cc + 1]       = acc[mi][ni][1];
            Ds[(r0 + 8) * DS_STRIDE + cc]     = acc[mi][ni][2];
            Ds[(r0 + 8) * DS_STRIDE + cc + 1] = acc[mi][ni][3];
        }
    }
    __syncthreads();

    float* db = d_dist + (size_t)b * NN * NN;
    const float* sqb = d_sq + b * NN;

    if (blockIdx.x != blockIdx.y) {
        for (int cl = w; cl < 128; cl += 8) {
            int m = n0 + cl;
            if (m >= NN) continue;
            float* dbm = db + (size_t)m * NN;
            const int yc = yyC[cl], xc = xxC[cl];
#pragma unroll
            for (int rq = 0; rq < 4; rq++) {
                int rl = rq * 32 + lane;
                int rg = m0 + rl;
                if (rg >= NN) continue;
                float v = Ds[rl * DS_STRIDE + cl];
                float relv = Rs[yyR[rl] * 56 + yc] + Rs[xxR[rl] * 56 + xc];
                dbm[rg] = sqb[rg] - 2.0f * v + relv;
            }
        }
    }
    {
        const int c = tid & 127;
        const int rh = (tid >> 7) * 64;
        const int gc = n0 + c;
        if (gc < NN) {
            const float sqc = sqb[gc];
            const int yc = yyC[c], xc = xxC[c];
#pragma unroll 1
            for (int r = 0; r < 64; r++) {
                int rl = rh + r;
                int rg = m0 + rl;
                if (rg >= NN) break;
                float v = Ds[rl * DS_STRIDE + c];
                float relv = Rs[yyR[rl] * 56 + yc] + Rs[xxR[rl] * 56 + xc];
                db[(size_t)rg * NN + gc] = sqc - 2.0f * v + relv;
            }
        }
    }
}

// ---------------- fc mma kernel (fc1 / fc2) -----------------------------------
// SEGS = slabs per segment (fc1: 3, fc2: 6); EPI 0 = BN1->d_h, 1 = BN2+res->out
#define F_TOTAL (4 * TILE_B)           // 73728 (>= 128*133*4 staging)
template <int SEGS, int EPI>
__global__ void __launch_bounds__(256)
fc_mma_kernel(const float* __restrict__ q0, const float* __restrict__ q1,
              const float* __restrict__ q2, const float* __restrict__ q3,
              const float* __restrict__ q4,
              const float* __restrict__ xres, float* __restrict__ outp)
{
    constexpr int NS = 3 * SEGS;
    constexpr int ROWLEN = 2 * SEGS * 64;     // compact row elems (384/768)
    extern __shared__ char smem[];
    const int tid = threadIdx.x, w = tid >> 5, lane = tid & 31;
    const int m0 = blockIdx.y * 128, n0 = blockIdx.x * 128;

    const __nv_bfloat16* Asrc = (EPI == 0) ? d_xt : d_ya;
    const __nv_bfloat16* Bsrc = (EPI == 0) ? d_w1 : d_wb;

    const uint32_t sbuf = smem_u32(smem);
    const uint32_t sAq[2] = { sbuf, sbuf + TILE_B };
    const uint32_t sBq[2] = { sbuf + 2 * TILE_B, sbuf + 3 * TILE_B };

    auto issue = [&](int s) {
        const int offA = (s < 2 * SEGS) ? 64 * (s % SEGS) : 64 * SEGS + 64 * (s - 2 * SEGS);
        const int offB = (s < SEGS) ? 64 * s
                       : (s < 2 * SEGS) ? 64 * SEGS + 64 * (s - SEGS)
                       : 64 * (s - 2 * SEGS);
        const uint32_t dA = sAq[s & 1], dB = sBq[s & 1];
#pragma unroll
        for (int c = 0; c < 4; c++) {
            int ch = tid + c * 256;
            int row = ch >> 3, cg = (ch & 7) * 16;
            const char* ga = (const char*)(Asrc + (size_t)(m0 + row) * ROWLEN + offA) + cg;
            const char* gb = (const char*)(Bsrc + (size_t)min(n0 + row, CC - 1) * ROWLEN + offB) + cg;
            uint32_t off = row * SROW + cg;
            asm volatile("cp.async.cg.shared.global [%0], [%1], 16;" :: "r"(dA + off), "l"(ga));
            asm volatile("cp.async.cg.shared.global [%0], [%1], 16;" :: "r"(dB + off), "l"(gb));
        }
        asm volatile("cp.async.commit_group;" ::: "memory");
    };

    issue(0);
    issue(1);

    float acc[2][8][4];
#pragma unroll
    for (int i = 0; i < 2; i++)
#pragma unroll
        for (int j = 0; j < 8; j++)
#pragma unroll
            for (int k = 0; k < 4; k++) acc[i][j][k] = 0.0f;

    const int wm = w & 3;
    const int wn = w >> 2;
    const int aRow  = lane & 15;
    const int aColB = ((lane >> 4) * 8) * 2;
    const int bNr   = ((lane >> 4) << 3) + (lane & 7);
    const int bColB = (((lane >> 3) & 1) * 8) * 2;

    for (int s = 0; s < NS; s++) {
        if (s < NS - 1)
            asm volatile("cp.async.wait_group 1;" ::: "memory");
        else
            asm volatile("cp.async.wait_group 0;" ::: "memory");
        __syncthreads();
        const uint32_t cA = sAq[s & 1], cB = sBq[s & 1];
#pragma unroll
        for (int kk = 0; kk < 4; kk++) {
            const int k0b = kk * 32;
            uint32_t af[2][4];
#pragma unroll
            for (int mi = 0; mi < 2; mi++) {
                uint32_t addr = cA + (wm * 32 + mi * 16 + aRow) * SROW + k0b + aColB;
                asm volatile(
                    "ldmatrix.sync.aligned.m8n8.x4.shared.b16 {%0,%1,%2,%3}, [%4];"
                    : "=r"(af[mi][0]), "=r"(af[mi][1]), "=r"(af[mi][2]), "=r"(af[mi][3])
                    : "r"(addr));
            }
            uint32_t bfv[4][4];
#pragma unroll
            for (int nb = 0; nb < 4; nb++) {
                uint32_t addr = cB + (wn * 64 + nb * 16 + bNr) * SROW + k0b + bColB;
                asm volatile(
                    "ldmatrix.sync.aligned.m8n8.x4.shared.b16 {%0,%1,%2,%3}, [%4];"
                    : "=r"(bfv[nb][0]), "=r"(bfv[nb][1]), "=r"(bfv[nb][2]), "=r"(bfv[nb][3])
                    : "r"(addr));
            }
#pragma unroll
            for (int mi = 0; mi < 2; mi++)
#pragma unroll
                for (int ni = 0; ni < 8; ni++) {
                    uint32_t b0 = bfv[ni >> 1][(ni & 1) * 2 + 0];
                    uint32_t b1 = bfv[ni >> 1][(ni & 1) * 2 + 1];
                    asm volatile(
                        "mma.sync.aligned.m16n8k16.row.col.f32.bf16.bf16.f32 "
                        "{%0,%1,%2,%3}, {%4,%5,%6,%7}, {%8,%9}, {%0,%1,%2,%3};"
                        : "+f"(acc[mi][ni][0]), "+f"(acc[mi][ni][1]),
                          "+f"(acc[mi][ni][2]), "+f"(acc[mi][ni][3])
                        : "r"(af[mi][0]), "r"(af[mi][1]), "r"(af[mi][2]), "r"(af[mi][3]),
                          "r"(b0), "r"(b1));
                }
        }
        __syncthreads();
        if (s + 2 < NS) issue(s + 2);
    }

    float* Ds = reinterpret_cast<float*>(smem);
#pragma unroll
    for (int mi = 0; mi < 2; mi++) {
        int r0 = wm * 32 + mi * 16 + (lane >> 2);
        int c0 = wn * 64 + (lane & 3) * 2;
#pragma unroll
        for (int ni = 0; ni < 8; ni++) {
            int cc = c0 + ni * 8;
            Ds[r0 * DS_STRIDE + cc]           = acc[mi][ni][0];
            Ds[r0 * DS_STRIDE + cc + 1]       = acc[mi][ni][1];
            Ds[(r0 + 8) * DS_STRIDE + cc]     = acc[mi][ni][2];
            Ds[(r0 + 8) * DS_STRIDE + cc + 1] = acc[mi][ni][3];
        }
    }
    __syncthreads();

    if (EPI == 0) {
        // BN1 -> d_h row-major (coalesced along channels)
        const int col = tid & 127;
        const int gc = n0 + col;
        float s = 0.f, bi = 0.f;
        if (gc < CC) {
            s = q1[gc] * rsqrtf(q4[gc] + BNEPS);
            bi = (q0[gc] - q3[gc]) * s + q2[gc];
        }
        const int r0 = tid >> 7;              // 0 or 1
        if (gc < CC) {
#pragma unroll 1
            for (int it = 0; it < 64; it++) {
                int rl = r0 + it * 2;
                d_h[(size_t)(m0 + rl) * CC + gc] = Ds[rl * DS_STRIDE + col] * s + bi;
            }
        }
    } else {
        // BN2 + transposed residual write: warp = column, lanes = rows
        for (int cl = w; cl < 128; cl += 8) {
            int gc = n0 + cl;
            if (gc >= CC) continue;
            float s = q1[gc] * rsqrtf(q4[gc] + BNEPS);
            float bi = (q0[gc] - q3[gc]) * s + q2[gc];
#pragma unroll
            for (int rq = 0; rq < 4; rq++) {
                int rl = rq * 32 + lane;
                int rg = m0 + rl;
                int bb = rg / NN, nn2 = rg - bb * NN;
                size_t o = ((size_t)bb * CC + gc) * NN + nn2;
                float v = Ds[rl * DS_STRIDE + cl];
                outp[o] = v * s + bi + xres[o];
            }
        }
    }
}

// ---------------- fused top-9 + gather/max-edge (4 rows per block) -----------
__global__ void __launch_bounds__(256) topk_gather_kernel() {
    const int r = threadIdx.x >> 6;
    const int g = threadIdx.x & 63;
    const int row = blockIdx.x * 4 + r;
    const int b = row / NN, n = row % NN;
    const float4* dr4 = reinterpret_cast<const float4*>(
        d_dist + (size_t)b * NN * NN + (size_t)n * NN);

    float tv[KNB];
    int   ti[KNB];
#pragma unroll
    for (int q = 0; q < KNB; q++) { tv[q] = INFINITY; ti[q] = 0x7fffffff; }

    for (int i4 = g; i4 < NN / 4; i4 += 64) {
        float4 v4 = dr4[i4];
        const int mb = i4 * 4;
        float vv[4] = { v4.x, v4.y, v4.z, v4.w };
#pragma unroll
        for (int c = 0; c < 4; c++) {
            float v = vv[c];
            if (v < tv[KNB - 1]) {
                tv[KNB - 1] = v; ti[KNB - 1] = mb + c;
#pragma unroll
                for (int q = KNB - 1; q > 0; q--) {
                    if (tv[q] < tv[q - 1]) {
                        float fv = tv[q]; tv[q] = tv[q - 1]; tv[q - 1] = fv;
                        int   fi = ti[q]; ti[q] = ti[q - 1]; ti[q - 1] = fi;
                    }
                }
            }
        }
    }

    __shared__ float sv[256 * KNB];
    __shared__ int   si[256 * KNB];
#pragma unroll
    for (int q = 0; q < KNB; q++) {
        sv[threadIdx.x * KNB + q] = tv[q];
        si[threadIdx.x * KNB + q] = ti[q];
    }

    for (int stride = 32; stride >= 1; stride >>= 1) {
        __syncthreads();
        if (g < (unsigned)stride) {
            float* Av = &sv[(r * 64 + g) * KNB];
            int*   Ai = &si[(r * 64 + g) * KNB];
            float* Bv = &sv[(r * 64 + g + stride) * KNB];
            int*   Bi = &si[(r * 64 + g + stride) * KNB];
            float ov[KNB]; int oi[KNB];
            int ia = 0, ib = 0;
#pragma unroll
            for (int q = 0; q < KNB; q++) {
                float va = (ia < KNB) ? Av[ia] : INFINITY;
                float vb = (ib < KNB) ? Bv[ib] : INFINITY;
                int xa = (ia < KNB) ? Ai[ia] : 0x7fffffff;
                int xb = (ib < KNB) ? Bi[ib] : 0x7fffffff;
                bool takeA = (va < vb) || (va == vb && xa < xb);
                ov[q] = takeA ? va : vb;
                oi[q] = takeA ? xa : xb;
                if (takeA) ia++; else ib++;
            }
#pragma unroll
            for (int q = 0; q < KNB; q++) { Av[q] = ov[q]; Ai[q] = oi[q]; }
        }
    }
    __syncthreads();

    {
        const int* nn9 = &si[(r * 64) * KNB];
        const float* hb = d_h + (size_t)b * NN * CC;
        const float* hr = d_h + (size_t)row * CC;
        float* gb = d_gbuf + (size_t)row * CC2;
#pragma unroll
        for (int e = 0; e < 3; e++) {
            int c = g + e * 64;
            float hn = hr[c];
            float mx = -INFINITY;
#pragma unroll
            for (int j = 0; j < KNB; j++)
                mx = fmaxf(mx, hb[(size_t)nn9[j] * CC + c] - hn);
            gb[c]      = hn;
            gb[CC + c] = mx;
        }
    }
}

// ---------------- launch ----------------------------------------------------
extern "C" void kernel_launch(void* const* d_in, const int* in_sizes, int n_in,
                              void* d_out, int out_size)
{
    (void)in_sizes; (void)n_in; (void)out_size;
    const float* x     = (const float*)d_in[0];
    const float* fc1_w = (const float*)d_in[1];
    const float* fc1_b = (const float*)d_in[2];
    const float* bn1_g = (const float*)d_in[3];
    const float* bn1_b = (const float*)d_in[4];
    const float* bn1_m = (const float*)d_in[5];
    const float* bn1_v = (const float*)d_in[6];
    const float* gc_w  = (const float*)d_in[7];
    const float* gc_b  = (const float*)d_in[8];
    const float* bng_g = (const float*)d_in[9];
    const float* bng_b = (const float*)d_in[10];
    const float* bng_m = (const float*)d_in[11];
    const float* bng_v = (const float*)d_in[12];
    const float* fc2_w = (const float*)d_in[13];
    const float* fc2_b = (const float*)d_in[14];
    const float* bn2_g = (const float*)d_in[15];
    const float* bn2_b = (const float*)d_in[16];
    const float* bn2_m = (const float*)d_in[17];
    const float* bn2_v = (const float*)d_in[18];
    float* out = (float*)d_out;

    cudaFuncSetAttribute(dist_mma_kernel,
                         cudaFuncAttributeMaxDynamicSharedMemorySize, DSM_TOTAL);
    cudaFuncSetAttribute(fc_mma_kernel<3, 0>,
                         cudaFuncAttributeMaxDynamicSharedMemorySize, F_TOTAL);
    cudaFuncSetAttribute(fc_mma_kernel<6, 1>,
                         cudaFuncAttributeMaxDynamicSharedMemorySize, F_TOTAL);

    // 1: rel position table
    rel_table_kernel<<<25, 128>>>();
    // 2: split fc1_w
    w1split_kernel<<<(CC * CC + 255) / 256, 256>>>(fc1_w);
    // 3: transpose-split x -> d_xt
    xt_split_kernel<<<dim3(98, 6, BB), dim3(32, 8)>>>(x);
    // 4: fc1 via mma + bn1 -> d_h   [ncu capture slot]
    fc_mma_kernel<3, 0><<<dim3(2, 196), 256, F_TOTAL>>>(fc1_b, bn1_g, bn1_b, bn1_m, bn1_v, nullptr, nullptr);
    // 5: normalize rows -> sq + d_xc split
    norm_kernel<<<MTOT, 64>>>();
    // 6: dist via mma (compact buffers)
    dist_mma_kernel<<<dim3(25, 25, BB), 256, DSM_TOTAL>>>();
    // 7: split fc2_w
    wsplit_kernel<<<(CC * CC2 + 255) / 256, 256>>>(fc2_w);
    // 8: fused top-9 + gather/max-edge -> g = [h, d]
    topk_gather_kernel<<<MTOT / 4, 256>>>();
    // 9: grouped conv + bn + gelu -> d_ya split
    group_gemm_kernel<<<dim3(1, 25, BB * 4), 256>>>(gc_w, gc_b, bng_g, bng_b, bng_m, bng_v);
    // 10: fc2 via mma + bn2 + transpose + residual -> out
    fc_mma_kernel<6, 1><<<dim3(2, 196), 256, F_TOTAL>>>(fc2_b, bn2_g, bn2_b, bn2_m, bn2_v, x, out);
}